// round 5
// baseline (speedup 1.0000x reference)
#include <cuda_runtime.h>
#include <cuda_bf16.h>
#include <math.h>
#include <stdint.h>

// ---------------- constants ----------------
#define B_ROWS   16384
#define D_DIM    1024
#define K3       3072           // 3-way split K (bf16 triplets)
#define K3U      1536           // uints per split row
#define NCAT     3584           // 1024(Wc1)+1024(Wr1)+1024(Wa)+512(Wo1)
#define ORD_H    512
#define N_EXP    7
#define MAX_TILES 136
#define MAX_SLOTS (MAX_TILES*128)
#define KITERS   96             // K3 / 32

// ---------------- scratch (floats) ----------------
#define OFF_HB    0LL                      // Hbig [16384][3584] fp32
#define OFF_X3    58720256LL               // X3 triplet  [16384][1536] uints
#define OFF_DFC   83886080LL               // Dfc triplet [17408][1536] uints
#define OFF_H1F   110624768LL              // H1 fp32 [17408][1024]
#define OFF_H13   128450560LL              // H1 triplet [17408][1536] uints
#define OFF_H2    155189248LL              // H2 fp32 [17408][1024]
#define OFF_WCAT  173015040LL              // Wcat bf16 [3584][3072]
#define OFF_WE1   178520064LL              // We1 triplet bf16 [7][1024][3072]
#define OFF_WE2   189530112LL
#define OFF_BCAT  200540160LL              // bcat fp32 [3584]
#define TOTAL_F   200543744LL

__device__ __align__(1024) float g_buf[TOTAL_F];

__device__ int d_size_idx[B_ROWS];
__device__ int d_perm[MAX_SLOTS];
__device__ int d_tile_expert[MAX_TILES];
__device__ int d_count[N_EXP];
__device__ int d_cursor[N_EXP];
__device__ int d_off[N_EXP];
__device__ int d_fix_count;
__device__ int d_fix_rows[B_ROWS];

// ---------------- baseline-PTX helpers ----------------
__device__ __forceinline__ uint32_t smem_to_u32(const void* p) {
    uint32_t a;
    asm("{ .reg .u64 t; cvta.to.shared.u64 t, %1; cvt.u32.u64 %0, t; }" : "=r"(a) : "l"(p));
    return a;
}
#define CP_ASYNC16(dst, src) \
    asm volatile("cp.async.cg.shared.global [%0], [%1], 16;" :: "r"(dst), "l"(src))
#define CP_COMMIT() asm volatile("cp.async.commit_group;" ::: "memory")
#define CP_WAIT2()  asm volatile("cp.async.wait_group 2;" ::: "memory")

#define LDSM_X4(r0, r1, r2, r3, addr) \
    asm volatile("ldmatrix.sync.aligned.m8n8.x4.shared.b16 {%0,%1,%2,%3}, [%4];" \
        : "=r"(r0), "=r"(r1), "=r"(r2), "=r"(r3) : "r"(addr))

#define MMA_BF16(d, a, b) \
    asm volatile("mma.sync.aligned.m16n8k16.row.col.f32.bf16.bf16.f32 " \
        "{%0,%1,%2,%3}, {%4,%5,%6,%7}, {%8,%9}, {%0,%1,%2,%3};" \
        : "+f"((d)[0]), "+f"((d)[1]), "+f"((d)[2]), "+f"((d)[3]) \
        : "r"((a)[0]), "r"((a)[1]), "r"((a)[2]), "r"((a)[3]), "r"((b)[0]), "r"((b)[1]))

// ---------------- split helpers ----------------
__device__ __forceinline__ unsigned pack_split(float v) {
    __nv_bfloat16 hi = __float2bfloat16_rn(v);
    __nv_bfloat16 lo = __float2bfloat16_rn(v - __bfloat162float(hi));
    return (unsigned)__bfloat16_as_ushort(hi) | ((unsigned)__bfloat16_as_ushort(lo) << 16);
}
// A-triplet stream (hi,lo,hi) from packed (hi|lo) pairs
__device__ __forceinline__ unsigned trip_uint(const unsigned* pairs, int u) {
    const int t = u / 3, rm = u - 3 * t;
    const unsigned p0 = pairs[2 * t], p1 = pairs[2 * t + 1];
    if (rm == 0) return p0;                          // hi(2t) | lo(2t)
    if (rm == 1) return __byte_perm(p0, p1, 0x5410); // hi(2t) | hi(2t+1)
    return __byte_perm(p1, p1, 0x1032);              // lo(2t+1) | hi(2t+1)
}

// ---------------- conversions ----------------
__global__ void conv_x_kernel(const float* __restrict__ in, unsigned* __restrict__ out)
{
    __shared__ unsigned stg[1024];
    const int row = blockIdx.x;
    const float* xr = in + (size_t)row * D_DIM;
    for (int e = threadIdx.x; e < D_DIM; e += 256) stg[e] = pack_split(xr[e]);
    __syncthreads();
    unsigned* orow = out + (size_t)row * K3U;
    for (int u = threadIdx.x; u < K3U; u += 256) orow[u] = trip_uint(stg, u);
}

// W [K,N] fp32 -> out [N][3K] bf16 W-triplet (hi,hi,lo); grid.z = expert
__global__ void conv_w_kernel(const float* __restrict__ W, __nv_bfloat16* __restrict__ out,
                              int K, int N)
{
    __shared__ float t[32][33];
    const int k0 = blockIdx.x * 32, n0 = blockIdx.y * 32;
    W   += (size_t)blockIdx.z * K * N;
    out += (size_t)blockIdx.z * N * 3 * K;
    for (int r = threadIdx.y; r < 32; r += 8)
        t[r][threadIdx.x] = W[(size_t)(k0 + r) * N + n0 + threadIdx.x];
    __syncthreads();
    for (int r = threadIdx.y; r < 32; r += 8) {
        const float w = t[threadIdx.x][r];
        __nv_bfloat16 hi = __float2bfloat16_rn(w);
        __nv_bfloat16 lo = __float2bfloat16_rn(w - __bfloat162float(hi));
        __nv_bfloat16* o = out + (size_t)(n0 + r) * 3 * K + 3 * (k0 + threadIdx.x);
        o[0] = hi; o[1] = hi; o[2] = lo;
    }
}

// fused conversion of all four stage-1 weights into Wcat [3584][3072]
__global__ void conv_wcat_kernel(const float* __restrict__ Wc1, const float* __restrict__ Wr1,
                                 const float* __restrict__ Wa, const float* __restrict__ Wo1,
                                 __nv_bfloat16* __restrict__ out)
{
    __shared__ float t[32][33];
    const int k0 = blockIdx.x * 32;
    const int nc0 = blockIdx.y * 32;          // global concat col
    const float* W; int N; int nl;
    if (nc0 < 1024)      { W = Wc1; N = 1024; nl = nc0; }
    else if (nc0 < 2048) { W = Wr1; N = 1024; nl = nc0 - 1024; }
    else if (nc0 < 3072) { W = Wa;  N = 1024; nl = nc0 - 2048; }
    else                 { W = Wo1; N = 512;  nl = nc0 - 3072; }
    for (int r = threadIdx.y; r < 32; r += 8)
        t[r][threadIdx.x] = W[(size_t)(k0 + r) * N + nl + threadIdx.x];
    __syncthreads();
    for (int r = threadIdx.y; r < 32; r += 8) {
        const float w = t[threadIdx.x][r];
        __nv_bfloat16 hi = __float2bfloat16_rn(w);
        __nv_bfloat16 lo = __float2bfloat16_rn(w - __bfloat162float(hi));
        __nv_bfloat16* o = out + (size_t)(nc0 + r) * K3 + 3 * (k0 + threadIdx.x);
        o[0] = hi; o[1] = hi; o[2] = lo;
    }
}

__global__ void bias_cat_kernel(const float* bc1, const float* br1,
                                const float* ba, const float* bo1, float* bcat)
{
    const int i = blockIdx.x * 256 + threadIdx.x;
    if (i < 1024)      bcat[i] = bc1[i];
    else if (i < 2048) bcat[i] = br1[i - 1024];
    else if (i < 3072) bcat[i] = ba[i - 2048];
    else if (i < 3584) bcat[i] = bo1[i - 3072];
}

// gather Df rows (Hbig cols 2048..3071) through perm, emit compact triplet rows
__global__ void gather_kernel(const float* __restrict__ HB, unsigned* __restrict__ out)
{
    __shared__ unsigned stg[1024];
    const int slot = blockIdx.x;
    const int p = d_perm[slot];
    const float* r = HB + (size_t)(p < 0 ? 0 : p) * NCAT + 2048;
    for (int e = threadIdx.x; e < D_DIM; e += 256) stg[e] = (p < 0) ? 0u : pack_split(r[e]);
    __syncthreads();
    unsigned* o = out + (size_t)slot * K3U;
    for (int u = threadIdx.x; u < K3U; u += 256) o[u] = trip_uint(stg, u);
}

// H1 fp32 -> triplet
__global__ void conv_h1_kernel(const float* __restrict__ in, unsigned* __restrict__ out)
{
    __shared__ unsigned stg[1024];
    const int row = blockIdx.x;
    const float* r = in + (size_t)row * D_DIM;
    for (int e = threadIdx.x; e < D_DIM; e += 256) stg[e] = pack_split(r[e]);
    __syncthreads();
    unsigned* o = out + (size_t)row * K3U;
    for (int u = threadIdx.x; u < K3U; u += 256) o[u] = trip_uint(stg, u);
}

// ---------------- HMMA GEMM: C = relu(A_trip @ W_trip^T + bias) ----------------
// 128 threads (4 warps), tile 128x128, warp tile 64x64, BK=32, 4-stage cp.async
#define STAGE_B   20480                // (128 A rows + 128 B rows) * 80B
#define GSMEM_SZ  (STAGE_B * 4)

__global__ __launch_bounds__(128, 2)
void gemm_hmma(const __nv_bfloat16* __restrict__ A,
               const __nv_bfloat16* __restrict__ Bw,
               const float* __restrict__ biasBase,
               float* __restrict__ C, int ldc,
               int useExpert, long long wStride, int biasStride)
{
    extern __shared__ __align__(128) unsigned char smem[];
    const int tileN = blockIdx.x, tileM = blockIdx.y;
    int e = 0;
    if (useExpert) { e = d_tile_expert[tileM]; if (e < 0) return; }

    const __nv_bfloat16* Ap = A + (size_t)tileM * 128 * K3;
    const __nv_bfloat16* Bp = Bw + (size_t)e * wStride + (size_t)tileN * 128 * K3;
    const float* bias = biasBase + (size_t)e * biasStride;

    const uint32_t sbase = smem_to_u32(smem);
    const int tid = threadIdx.x, wid = tid >> 5, lane = tid & 31;
    const int wm = wid >> 1, wn = wid & 1;
    const int lrow = lane & 15, lcol = lane >> 4;

    auto issue = [&](int kt) {
        const uint32_t base = sbase + (kt & 3) * STAGE_B;
        const int k0 = kt * 32;
        #pragma unroll
        for (int p = 0; p < 4; p++) {
            const int c = tid + p * 128;
            const int r = c >> 2, s = c & 3;
            CP_ASYNC16(base + r * 80 + s * 16,         Ap + (size_t)r * K3 + k0 + s * 8);
            CP_ASYNC16(base + 10240 + r * 80 + s * 16, Bp + (size_t)r * K3 + k0 + s * 8);
        }
    };

    float acc[4][8][4] = {};

    issue(0); CP_COMMIT();
    issue(1); CP_COMMIT();
    issue(2); CP_COMMIT();

    for (int kt = 0; kt < KITERS; kt++) {
        CP_WAIT2();
        __syncthreads();
        if (kt + 3 < KITERS) issue(kt + 3);
        CP_COMMIT();

        const uint32_t ab = sbase + (kt & 3) * STAGE_B;
        const uint32_t bb = ab + 10240;
        #pragma unroll
        for (int kk = 0; kk < 2; kk++) {
            uint32_t a[4][4];
            #pragma unroll
            for (int i = 0; i < 4; i++) {
                const uint32_t addr = ab + (wm * 64 + i * 16 + lrow) * 80 + (kk * 16 + lcol * 8) * 2;
                LDSM_X4(a[i][0], a[i][1], a[i][2], a[i][3], addr);
            }
            uint32_t b[8][2];
            #pragma unroll
            for (int j4 = 0; j4 < 4; j4++) {
                uint32_t q0, q1, q2, q3;
                const uint32_t addr = bb + (wn * 64 + j4 * 16 + lrow) * 80 + (kk * 16 + lcol * 8) * 2;
                LDSM_X4(q0, q1, q2, q3, addr);
                b[2 * j4][0] = q0;     b[2 * j4][1] = q2;
                b[2 * j4 + 1][0] = q1; b[2 * j4 + 1][1] = q3;
            }
            #pragma unroll
            for (int i = 0; i < 4; i++)
                #pragma unroll
                for (int j = 0; j < 8; j++)
                    MMA_BF16(acc[i][j], a[i], b[j]);
        }
    }

    // epilogue: bias + relu, float2 stores
    const int rbase = tileM * 128 + wm * 64 + (lane >> 2);
    const int cbase = tileN * 128 + wn * 64 + (lane & 3) * 2;
    #pragma unroll
    for (int j = 0; j < 8; j++) {
        const int col = cbase + j * 8;
        const float2 bz = *reinterpret_cast<const float2*>(bias + col);
        #pragma unroll
        for (int i = 0; i < 4; i++) {
            const int ra = rbase + i * 16;
            float2 v0, v1;
            v0.x = fmaxf(acc[i][j][0] + bz.x, 0.f);
            v0.y = fmaxf(acc[i][j][1] + bz.y, 0.f);
            v1.x = fmaxf(acc[i][j][2] + bz.x, 0.f);
            v1.y = fmaxf(acc[i][j][3] + bz.y, 0.f);
            *reinterpret_cast<float2*>(C + (size_t)ra * ldc + col) = v0;
            *reinterpret_cast<float2*>(C + (size_t)(ra + 8) * ldc + col) = v1;
        }
    }
}

// ---------------- fused head ----------------
__global__ void head_kernel(const float* __restrict__ HB,
                            const float* __restrict__ Wc2, const float* __restrict__ bc2,
                            const float* __restrict__ Wo2, const float* __restrict__ bo2,
                            const float* __restrict__ Wr2, const float* __restrict__ br2,
                            float* __restrict__ out)
{
    const int row = blockIdx.x * blockDim.y + threadIdx.y;
    if (row >= B_ROWS) return;
    const int lane = threadIdx.x;
    const float* hb = HB + (size_t)row * NCAT;

    float a[7] = {0,0,0,0,0,0,0};
    for (int k = lane; k < D_DIM; k += 32) {
        const float hv = hb[k]; const float* w = Wc2 + k * 7;
        #pragma unroll
        for (int c = 0; c < 7; c++) a[c] = fmaf(hv, w[c], a[c]);
    }
    float o[6] = {0,0,0,0,0,0};
    for (int k = lane; k < ORD_H; k += 32) {
        const float hv = hb[3072 + k]; const float* w = Wo2 + k * 6;
        #pragma unroll
        for (int c = 0; c < 6; c++) o[c] = fmaf(hv, w[c], o[c]);
    }
    float r = 0.f;
    for (int k = lane; k < D_DIM; k += 32) r = fmaf(hb[1024 + k], Wr2[k], r);

    #pragma unroll
    for (int off = 16; off; off >>= 1) {
        #pragma unroll
        for (int c = 0; c < 7; c++) a[c] += __shfl_xor_sync(0xffffffffu, a[c], off);
        #pragma unroll
        for (int c = 0; c < 6; c++) o[c] += __shfl_xor_sync(0xffffffffu, o[c], off);
        r += __shfl_xor_sync(0xffffffffu, r, off);
    }
    if (lane == 0) {
        float sl[7];
        #pragma unroll
        for (int c = 0; c < 7; c++) sl[c] = a[c] + bc2[c];
        float mx = sl[0];
        #pragma unroll
        for (int c = 1; c < 7; c++) mx = fmaxf(mx, sl[c]);
        float ex[7], s = 0.f;
        #pragma unroll
        for (int c = 0; c < 7; c++) { ex[c] = expf(sl[c] - mx); s += ex[c]; }
        const float inv = 1.f / s;

        float expected = 0.f;
        int idx = 0; float best = sl[0], best2 = -1e30f;
        float* orow = out + (size_t)row * 24;
        #pragma unroll
        for (int c = 0; c < 7; c++) {
            const float p = ex[c] * inv;
            expected = fmaf(p, (float)c * (1.0f / 6.0f), expected);
            orow[c] = sl[c];
            orow[14 + c] = p;
            if (c > 0) {
                if (sl[c] > best) { best2 = best; best = sl[c]; idx = c; }
                else if (sl[c] > best2) best2 = sl[c];
            }
        }
        #pragma unroll
        for (int c = 0; c < 6; c++) orow[7 + c] = o[c] + bo2[c];
        const float resid = 0.35f * tanhf(r + br2[0]);
        orow[13] = fminf(fmaxf(expected + resid, 0.f), 1.f);
        d_size_idx[row] = idx;
        if (best - best2 < 4e-3f) {
            int p = atomicAdd(&d_fix_count, 1);
            if (p < B_ROWS) d_fix_rows[p] = row;
        }
    }
}

// exact fp32 argmax recompute for near-tie rows
__global__ void fix_kernel(const float* __restrict__ x,
                           const float* __restrict__ Wc1, const float* __restrict__ bc1,
                           const float* __restrict__ Wc2, const float* __restrict__ bc2)
{
    __shared__ float xr[D_DIM];
    __shared__ float h[D_DIM];
    __shared__ float lg[8];
    int n = d_fix_count; if (n > B_ROWS) n = B_ROWS;
    for (int i = blockIdx.x; i < n; i += gridDim.x) {
        const int row = d_fix_rows[i];
        for (int k = threadIdx.x; k < D_DIM; k += 256) xr[k] = x[(size_t)row * D_DIM + k];
        __syncthreads();
        for (int j = threadIdx.x; j < D_DIM; j += 256) {
            float s = bc1[j];
            for (int k = 0; k < D_DIM; k++) s = fmaf(xr[k], Wc1[(size_t)k * D_DIM + j], s);
            h[j] = fmaxf(s, 0.f);
        }
        __syncthreads();
        const int w = threadIdx.x >> 5, l = threadIdx.x & 31;
        if (w < 7) {
            float s = 0.f;
            for (int k = l; k < D_DIM; k += 32) s = fmaf(h[k], Wc2[k * 7 + w], s);
            #pragma unroll
            for (int off = 16; off; off >>= 1) s += __shfl_xor_sync(0xffffffffu, s, off);
            if (!l) lg[w] = s + bc2[w];
        }
        __syncthreads();
        if (threadIdx.x == 0) {
            int idx = 0; float best = lg[0];
            #pragma unroll
            for (int c = 1; c < 7; c++) if (lg[c] > best) { best = lg[c]; idx = c; }
            d_size_idx[row] = idx;
        }
        __syncthreads();
    }
}

// ---------------- routing ----------------
__global__ void route_init_kernel()
{
    const int t = threadIdx.x;
    if (t < N_EXP) { d_count[t] = 0; d_cursor[t] = 0; d_off[t] = 0; }
    if (t < MAX_TILES) d_tile_expert[t] = -1;
    if (t == 0) d_fix_count = 0;
}
__global__ void perm_init_kernel()
{
    const int i = blockIdx.x * blockDim.x + threadIdx.x;
    if (i < MAX_SLOTS) d_perm[i] = -1;
}
__global__ void count_kernel()
{
    const int r = blockIdx.x * blockDim.x + threadIdx.x;
    if (r < B_ROWS) atomicAdd(&d_count[d_size_idx[r]], 1);
}
__global__ void scan_kernel()
{
    int off = 0;
    for (int e = 0; e < N_EXP; e++) {
        d_off[e] = off;
        const int tiles = (d_count[e] + 127) >> 7;
        const int base = off >> 7;
        for (int t = 0; t < tiles; t++) d_tile_expert[base + t] = e;
        off += tiles << 7;
    }
}
__global__ void scatter_kernel()
{
    const int r = blockIdx.x * blockDim.x + threadIdx.x;
    if (r < B_ROWS) {
        const int e = d_size_idx[r];
        const int pos = d_off[e] + atomicAdd(&d_cursor[e], 1);
        d_perm[pos] = r;
    }
}

// ---------------- depth final projection ----------------
__global__ void depth_final_kernel(const float* __restrict__ H2,
                                   const float* __restrict__ We3,
                                   const float* __restrict__ be3,
                                   float* __restrict__ out)
{
    const int slot = blockIdx.x * blockDim.y + threadIdx.y;
    if (slot >= MAX_SLOTS) return;
    const int e = d_tile_expert[slot >> 7];
    if (e < 0) return;
    const int p = d_perm[slot];
    if (p < 0) return;
    const int lane = threadIdx.x;
    float a0 = 0.f, a1 = 0.f, a2 = 0.f;
    const float* h = H2 + (size_t)slot * D_DIM;
    const float* w = We3 + (size_t)e * D_DIM * 3;
    for (int k = lane; k < D_DIM; k += 32) {
        const float hv = h[k];
        a0 = fmaf(hv, w[k * 3 + 0], a0);
        a1 = fmaf(hv, w[k * 3 + 1], a1);
        a2 = fmaf(hv, w[k * 3 + 2], a2);
    }
    #pragma unroll
    for (int off = 16; off; off >>= 1) {
        a0 += __shfl_xor_sync(0xffffffffu, a0, off);
        a1 += __shfl_xor_sync(0xffffffffu, a1, off);
        a2 += __shfl_xor_sync(0xffffffffu, a2, off);
    }
    if (lane == 0) {
        float* orow = out + (size_t)p * 24;
        orow[21] = a0 + be3[e * 3 + 0];
        orow[22] = a1 + be3[e * 3 + 1];
        orow[23] = a2 + be3[e * 3 + 2];
    }
}

// ---------------- launch ----------------
extern "C" void kernel_launch(void* const* d_in, const int* in_sizes, int n_in,
                              void* d_out, int out_size)
{
    const float* x   = (const float*)d_in[0];
    const float* Wc1 = (const float*)d_in[1];
    const float* bc1 = (const float*)d_in[2];
    const float* Wc2 = (const float*)d_in[3];
    const float* bc2 = (const float*)d_in[4];
    const float* Wo1 = (const float*)d_in[5];
    const float* bo1 = (const float*)d_in[6];
    const float* Wo2 = (const float*)d_in[7];
    const float* bo2 = (const float*)d_in[8];
    const float* Wr1 = (const float*)d_in[9];
    const float* br1 = (const float*)d_in[10];
    const float* Wr2 = (const float*)d_in[11];
    const float* br2 = (const float*)d_in[12];
    const float* Wa  = (const float*)d_in[13];
    const float* ba  = (const float*)d_in[14];
    const float* We1 = (const float*)d_in[15];
    const float* be1 = (const float*)d_in[16];
    const float* We2 = (const float*)d_in[17];
    const float* be2 = (const float*)d_in[18];
    const float* We3 = (const float*)d_in[19];
    const float* be3 = (const float*)d_in[20];
    float* out = (float*)d_out;

    float* buf = nullptr;
    cudaGetSymbolAddress((void**)&buf, g_buf);
    float*    HB   = buf + OFF_HB;
    unsigned* X3   = (unsigned*)(buf + OFF_X3);
    unsigned* Dfc  = (unsigned*)(buf + OFF_DFC);
    float*    H1f  = buf + OFF_H1F;
    unsigned* H13  = (unsigned*)(buf + OFF_H13);
    float*    H2   = buf + OFF_H2;
    __nv_bfloat16* Wcat = (__nv_bfloat16*)(buf + OFF_WCAT);
    __nv_bfloat16* W3e1 = (__nv_bfloat16*)(buf + OFF_WE1);
    __nv_bfloat16* W3e2 = (__nv_bfloat16*)(buf + OFF_WE2);
    float*    bcat = buf + OFF_BCAT;

    cudaFuncSetAttribute(gemm_hmma, cudaFuncAttributeMaxDynamicSharedMemorySize, GSMEM_SZ);

    // conversions (launch order keeps the big GEMM at launch #6 for ncu -s 5)
    conv_x_kernel<<<B_ROWS, 256>>>(x, X3);
    conv_wcat_kernel<<<dim3(32, 112), dim3(32, 8)>>>(Wc1, Wr1, Wa, Wo1, Wcat);
    conv_w_kernel<<<dim3(32, 32, N_EXP), dim3(32, 8)>>>(We1, W3e1, D_DIM, D_DIM);
    conv_w_kernel<<<dim3(32, 32, N_EXP), dim3(32, 8)>>>(We2, W3e2, D_DIM, D_DIM);
    bias_cat_kernel<<<14, 256>>>(bc1, br1, ba, bo1, bcat);

    // fused stage-1 GEMM: [16384 x 3584] = relu(X3 @ Wcat^T + bcat)
    gemm_hmma<<<dim3(NCAT / 128, B_ROWS / 128), 128, GSMEM_SZ>>>(
        (const __nv_bfloat16*)X3, Wcat, bcat, HB, NCAT, 0, 0, 0);

    // heads + near-tie fp32 fixup + routing tables
    route_init_kernel<<<1, 256>>>();
    head_kernel<<<B_ROWS / 8, dim3(32, 8)>>>(HB, Wc2, bc2, Wo2, bo2, Wr2, br2, out);
    fix_kernel<<<64, 256>>>(x, Wc1, bc1, Wc2, bc2);
    perm_init_kernel<<<(MAX_SLOTS + 255) / 256, 256>>>();
    count_kernel<<<(B_ROWS + 255) / 256, 256>>>();
    scan_kernel<<<1, 1>>>();
    scatter_kernel<<<(B_ROWS + 255) / 256, 256>>>();

    // expert dispatch + routed expert MLP (one expert per row)
    gather_kernel<<<MAX_SLOTS, 256>>>(HB, Dfc);
    gemm_hmma<<<dim3(8, MAX_TILES), 128, GSMEM_SZ>>>(
        (const __nv_bfloat16*)Dfc, W3e1, be1, H1f, D_DIM, 1, (long long)D_DIM * K3, D_DIM);
    conv_h1_kernel<<<MAX_SLOTS, 256>>>(H1f, H13);
    gemm_hmma<<<dim3(8, MAX_TILES), 128, GSMEM_SZ>>>(
        (const __nv_bfloat16*)H13, W3e2, be2, H2, D_DIM, 1, (long long)D_DIM * K3, D_DIM);

    // final 1024x3 projection scattered into output rows
    depth_final_kernel<<<MAX_SLOTS / 8, dim3(32, 8)>>>(H2, We3, be3, out);
}

// round 6
// speedup vs baseline: 1.3879x; 1.3879x over previous
#include <cuda_runtime.h>
#include <cuda_fp16.h>
#include <math.h>
#include <stdint.h>

// ---------------- constants ----------------
#define B_ROWS   16384
#define D_DIM    1024
#define K2       2048           // 2-way fp16 split K
#define K2U      1024           // uints per split row
#define NCAT     3584           // 1024(Wc1)+1024(Wr1)+1024(Wa)+512(Wo1)
#define ORD_H    512
#define N_EXP    7
#define MAX_TILES 136
#define MAX_SLOTS (MAX_TILES*128)
#define KITERS   64             // K2 / 32

// ---------------- scratch (floats) ----------------
#define OFF_HB    0LL                      // Hbig [16384][3584] fp32
#define OFF_X2    58720256LL               // X2 pairs [16384][1024] uints
#define OFF_DFC   75497472LL               // Dfc pairs [17408][1024] uints
#define OFF_H1F   93323264LL               // H1 fp32 [17408][1024]
#define OFF_H12   111149056LL              // H1 pairs [17408][1024] uints
#define OFF_H2    128974848LL              // H2 fp32 [17408][1024]
#define OFF_WCAT  146800640LL              // Wcat fp16 [3584][2048]
#define OFF_WE1   150470656LL              // We1 fp16 [7][1024][2048]
#define OFF_WE2   157810688LL
#define OFF_BCAT  165150720LL              // bcat fp32 [3584]
#define TOTAL_F   165154304LL

__device__ __align__(1024) float g_buf[TOTAL_F];

__device__ int d_size_idx[B_ROWS];
__device__ int d_perm[MAX_SLOTS];
__device__ int d_tile_expert[MAX_TILES];
__device__ int d_count[N_EXP];
__device__ int d_cursor[N_EXP];
__device__ int d_off[N_EXP];
__device__ int d_fix_count;
__device__ int d_fix_rows[B_ROWS];

// ---------------- baseline-PTX helpers ----------------
__device__ __forceinline__ uint32_t smem_to_u32(const void* p) {
    uint32_t a;
    asm("{ .reg .u64 t; cvta.to.shared.u64 t, %1; cvt.u32.u64 %0, t; }" : "=r"(a) : "l"(p));
    return a;
}
#define CP_ASYNC16(dst, src) \
    asm volatile("cp.async.cg.shared.global [%0], [%1], 16;" :: "r"(dst), "l"(src))
#define CP_COMMIT() asm volatile("cp.async.commit_group;" ::: "memory")
#define CP_WAIT2()  asm volatile("cp.async.wait_group 2;" ::: "memory")

#define LDSM_X4(r0, r1, r2, r3, addr) \
    asm volatile("ldmatrix.sync.aligned.m8n8.x4.shared.b16 {%0,%1,%2,%3}, [%4];" \
        : "=r"(r0), "=r"(r1), "=r"(r2), "=r"(r3) : "r"(addr))

#define MMA_F16(d, a, b) \
    asm volatile("mma.sync.aligned.m16n8k16.row.col.f32.f16.f16.f32 " \
        "{%0,%1,%2,%3}, {%4,%5,%6,%7}, {%8,%9}, {%0,%1,%2,%3};" \
        : "+f"((d)[0]), "+f"((d)[1]), "+f"((d)[2]), "+f"((d)[3]) \
        : "r"((a)[0]), "r"((a)[1]), "r"((a)[2]), "r"((a)[3]), "r"((b)[0]), "r"((b)[1]))

// ---------------- fp16 split helpers ----------------
// A pair (hi, lo): v = hi + lo to fp16 double precision (~2^-22)
__device__ __forceinline__ unsigned pack_pair_a(float v) {
    __half hi = __float2half_rn(v);
    __half lo = __float2half_rn(v - __half2float(hi));
    return (unsigned)__half_as_ushort(hi) | ((unsigned)__half_as_ushort(lo) << 16);
}
// W pair (hi, hi): pairs with A's (hi, lo) -> (a_hi + a_lo) * w_hi = a * w_hi
__device__ __forceinline__ unsigned pack_pair_w(float v) {
    const unsigned h = (unsigned)__half_as_ushort(__float2half_rn(v));
    return h | (h << 16);
}

// ---------------- conversions ----------------
// x fp32 row [1024] -> pair row [2048] fp16 (1024 uints)
__global__ void conv_x_kernel(const float* __restrict__ in, unsigned* __restrict__ out)
{
    const size_t i = (size_t)blockIdx.x * 256 + threadIdx.x;   // float4 index
    const float4 v = reinterpret_cast<const float4*>(in)[i];
    uint4 o;
    o.x = pack_pair_a(v.x); o.y = pack_pair_a(v.y);
    o.z = pack_pair_a(v.z); o.w = pack_pair_a(v.w);
    reinterpret_cast<uint4*>(out)[i] = o;
}

// W [K,N] fp32 -> out [N][2K] fp16 (w_hi, w_hi); grid.z = expert
__global__ void conv_w_kernel(const float* __restrict__ W, unsigned* __restrict__ out,
                              int K, int N)
{
    __shared__ float t[32][33];
    const int k0 = blockIdx.x * 32, n0 = blockIdx.y * 32;
    W   += (size_t)blockIdx.z * K * N;
    out += (size_t)blockIdx.z * N * K;         // uints: K per row
    for (int r = threadIdx.y; r < 32; r += 8)
        t[r][threadIdx.x] = W[(size_t)(k0 + r) * N + n0 + threadIdx.x];
    __syncthreads();
    for (int r = threadIdx.y; r < 32; r += 8)
        out[(size_t)(n0 + r) * K + k0 + threadIdx.x] = pack_pair_w(t[threadIdx.x][r]);
}

// fused conversion of all four stage-1 weights into Wcat [3584][2048]
__global__ void conv_wcat_kernel(const float* __restrict__ Wc1, const float* __restrict__ Wr1,
                                 const float* __restrict__ Wa, const float* __restrict__ Wo1,
                                 unsigned* __restrict__ out)
{
    __shared__ float t[32][33];
    const int k0 = blockIdx.x * 32;
    const int nc0 = blockIdx.y * 32;
    const float* W; int N; int nl;
    if (nc0 < 1024)      { W = Wc1; N = 1024; nl = nc0; }
    else if (nc0 < 2048) { W = Wr1; N = 1024; nl = nc0 - 1024; }
    else if (nc0 < 3072) { W = Wa;  N = 1024; nl = nc0 - 2048; }
    else                 { W = Wo1; N = 512;  nl = nc0 - 3072; }
    for (int r = threadIdx.y; r < 32; r += 8)
        t[r][threadIdx.x] = W[(size_t)(k0 + r) * N + nl + threadIdx.x];
    __syncthreads();
    for (int r = threadIdx.y; r < 32; r += 8)
        out[(size_t)(nc0 + r) * D_DIM + k0 + threadIdx.x] = pack_pair_w(t[threadIdx.x][r]);
}

__global__ void bias_cat_kernel(const float* bc1, const float* br1,
                                const float* ba, const float* bo1, float* bcat)
{
    const int i = blockIdx.x * 256 + threadIdx.x;
    if (i < 1024)      bcat[i] = bc1[i];
    else if (i < 2048) bcat[i] = br1[i - 1024];
    else if (i < 3072) bcat[i] = ba[i - 2048];
    else if (i < 3584) bcat[i] = bo1[i - 3072];
}

// gather Df rows (Hbig cols 2048..3071) through perm, emit compact pair rows
__global__ void gather_kernel(const float* __restrict__ HB, unsigned* __restrict__ out)
{
    const int slot = blockIdx.x;
    const int p = d_perm[slot];
    uint4 o = make_uint4(0u, 0u, 0u, 0u);
    if (p >= 0) {
        const float4 v = reinterpret_cast<const float4*>(
            HB + (size_t)p * NCAT + 2048)[threadIdx.x];
        o.x = pack_pair_a(v.x); o.y = pack_pair_a(v.y);
        o.z = pack_pair_a(v.z); o.w = pack_pair_a(v.w);
    }
    reinterpret_cast<uint4*>(out + (size_t)slot * K2U)[threadIdx.x] = o;
}

// H1 fp32 -> pairs
__global__ void conv_h1_kernel(const float* __restrict__ in, unsigned* __restrict__ out)
{
    const size_t i = (size_t)blockIdx.x * 256 + threadIdx.x;
    const float4 v = reinterpret_cast<const float4*>(in)[i];
    uint4 o;
    o.x = pack_pair_a(v.x); o.y = pack_pair_a(v.y);
    o.z = pack_pair_a(v.z); o.w = pack_pair_a(v.w);
    reinterpret_cast<uint4*>(out)[i] = o;
}

// ---------------- HMMA GEMM: C = relu(A_pair @ W_pair^T + bias) ----------------
// A: [Mtiles*128][K2] fp16, B: [N][K2] fp16, C fp32 [., ldc]
// 256 threads / 8 warps (warp 32x64), tile 128x128, BK=32, 4-stage cp.async
#define STAGE_B   20480                // (128 A rows + 128 B rows) * 80B
#define GSMEM_SZ  (STAGE_B * 4)

__global__ __launch_bounds__(256, 2)
void gemm_hmma(const __half* __restrict__ A,
               const __half* __restrict__ Bw,
               const float* __restrict__ biasBase,
               float* __restrict__ C, int ldc,
               int useExpert, long long wStride, int biasStride)
{
    extern __shared__ __align__(128) unsigned char smem[];
    const int tileN = blockIdx.x, tileM = blockIdx.y;
    int e = 0;
    if (useExpert) { e = d_tile_expert[tileM]; if (e < 0) return; }

    const __half* Ap = A + (size_t)tileM * 128 * K2;
    const __half* Bp = Bw + (size_t)e * wStride + (size_t)tileN * 128 * K2;
    const float* bias = biasBase + (size_t)e * biasStride;

    const uint32_t sbase = smem_to_u32(smem);
    const int tid = threadIdx.x, wid = tid >> 5, lane = tid & 31;
    const int wm = wid >> 1, wn = wid & 1;
    const int lrow = lane & 15, lcol = lane >> 4;

    // cp.async mapping: 2 chunks per thread per operand (4 chunks of 16B per row)
    const int ch0 = tid, ch1 = tid + 256;
    const int r0c = ch0 >> 2, s0c = ch0 & 3;
    const int r1c = ch1 >> 2, s1c = ch1 & 3;

    auto issue = [&](int kt) {
        const uint32_t base = sbase + (kt & 3) * STAGE_B;
        const int k0 = kt * 32;
        CP_ASYNC16(base + r0c * 80 + s0c * 16,         Ap + (size_t)r0c * K2 + k0 + s0c * 8);
        CP_ASYNC16(base + r1c * 80 + s1c * 16,         Ap + (size_t)r1c * K2 + k0 + s1c * 8);
        CP_ASYNC16(base + 10240 + r0c * 80 + s0c * 16, Bp + (size_t)r0c * K2 + k0 + s0c * 8);
        CP_ASYNC16(base + 10240 + r1c * 80 + s1c * 16, Bp + (size_t)r1c * K2 + k0 + s1c * 8);
    };

    float acc[2][8][4] = {};

    issue(0); CP_COMMIT();
    issue(1); CP_COMMIT();
    issue(2); CP_COMMIT();

    for (int kt = 0; kt < KITERS; kt++) {
        CP_WAIT2();
        __syncthreads();
        if (kt + 3 < KITERS) issue(kt + 3);
        CP_COMMIT();

        const uint32_t ab = sbase + (kt & 3) * STAGE_B;
        const uint32_t bb = ab + 10240;
        #pragma unroll
        for (int kk = 0; kk < 2; kk++) {
            uint32_t a[2][4];
            #pragma unroll
            for (int i = 0; i < 2; i++) {
                const uint32_t addr = ab + (wm * 32 + i * 16 + lrow) * 80 + (kk * 16 + lcol * 8) * 2;
                LDSM_X4(a[i][0], a[i][1], a[i][2], a[i][3], addr);
            }
            uint32_t b[8][2];
            #pragma unroll
            for (int j4 = 0; j4 < 4; j4++) {
                uint32_t q0, q1, q2, q3;
                const uint32_t addr = bb + (wn * 64 + j4 * 16 + lrow) * 80 + (kk * 16 + lcol * 8) * 2;
                LDSM_X4(q0, q1, q2, q3, addr);
                b[2 * j4][0] = q0;     b[2 * j4][1] = q2;
                b[2 * j4 + 1][0] = q1; b[2 * j4 + 1][1] = q3;
            }
            #pragma unroll
            for (int i = 0; i < 2; i++)
                #pragma unroll
                for (int j = 0; j < 8; j++)
                    MMA_F16(acc[i][j], a[i], b[j]);
        }
    }

    // epilogue: bias + relu, float2 stores
    const int rbase = tileM * 128 + wm * 32 + (lane >> 2);
    const int cbase = tileN * 128 + wn * 64 + (lane & 3) * 2;
    #pragma unroll
    for (int j = 0; j < 8; j++) {
        const int col = cbase + j * 8;
        const float2 bz = *reinterpret_cast<const float2*>(bias + col);
        #pragma unroll
        for (int i = 0; i < 2; i++) {
            const int ra = rbase + i * 16;
            float2 v0, v1;
            v0.x = fmaxf(acc[i][j][0] + bz.x, 0.f);
            v0.y = fmaxf(acc[i][j][1] + bz.y, 0.f);
            v1.x = fmaxf(acc[i][j][2] + bz.x, 0.f);
            v1.y = fmaxf(acc[i][j][3] + bz.y, 0.f);
            *reinterpret_cast<float2*>(C + (size_t)ra * ldc + col) = v0;
            *reinterpret_cast<float2*>(C + (size_t)(ra + 8) * ldc + col) = v1;
        }
    }
}

// ---------------- fused head ----------------
__global__ void head_kernel(const float* __restrict__ HB,
                            const float* __restrict__ Wc2, const float* __restrict__ bc2,
                            const float* __restrict__ Wo2, const float* __restrict__ bo2,
                            const float* __restrict__ Wr2, const float* __restrict__ br2,
                            float* __restrict__ out)
{
    const int row = blockIdx.x * blockDim.y + threadIdx.y;
    if (row >= B_ROWS) return;
    const int lane = threadIdx.x;
    const float* hb = HB + (size_t)row * NCAT;

    float a[7] = {0,0,0,0,0,0,0};
    for (int k = lane; k < D_DIM; k += 32) {
        const float hv = hb[k]; const float* w = Wc2 + k * 7;
        #pragma unroll
        for (int c = 0; c < 7; c++) a[c] = fmaf(hv, w[c], a[c]);
    }
    float o[6] = {0,0,0,0,0,0};
    for (int k = lane; k < ORD_H; k += 32) {
        const float hv = hb[3072 + k]; const float* w = Wo2 + k * 6;
        #pragma unroll
        for (int c = 0; c < 6; c++) o[c] = fmaf(hv, w[c], o[c]);
    }
    float r = 0.f;
    for (int k = lane; k < D_DIM; k += 32) r = fmaf(hb[1024 + k], Wr2[k], r);

    #pragma unroll
    for (int off = 16; off; off >>= 1) {
        #pragma unroll
        for (int c = 0; c < 7; c++) a[c] += __shfl_xor_sync(0xffffffffu, a[c], off);
        #pragma unroll
        for (int c = 0; c < 6; c++) o[c] += __shfl_xor_sync(0xffffffffu, o[c], off);
        r += __shfl_xor_sync(0xffffffffu, r, off);
    }
    if (lane == 0) {
        float sl[7];
        #pragma unroll
        for (int c = 0; c < 7; c++) sl[c] = a[c] + bc2[c];
        float mx = sl[0];
        #pragma unroll
        for (int c = 1; c < 7; c++) mx = fmaxf(mx, sl[c]);
        float ex[7], s = 0.f;
        #pragma unroll
        for (int c = 0; c < 7; c++) { ex[c] = expf(sl[c] - mx); s += ex[c]; }
        const float inv = 1.f / s;

        float expected = 0.f;
        int idx = 0; float best = sl[0], best2 = -1e30f;
        float* orow = out + (size_t)row * 24;
        #pragma unroll
        for (int c = 0; c < 7; c++) {
            const float p = ex[c] * inv;
            expected = fmaf(p, (float)c * (1.0f / 6.0f), expected);
            orow[c] = sl[c];
            orow[14 + c] = p;
            if (c > 0) {
                if (sl[c] > best) { best2 = best; best = sl[c]; idx = c; }
                else if (sl[c] > best2) best2 = sl[c];
            }
        }
        #pragma unroll
        for (int c = 0; c < 6; c++) orow[7 + c] = o[c] + bo2[c];
        const float resid = 0.35f * tanhf(r + br2[0]);
        orow[13] = fminf(fmaxf(expected + resid, 0.f), 1.f);
        d_size_idx[row] = idx;
        if (best - best2 < 4e-3f) {
            int p = atomicAdd(&d_fix_count, 1);
            if (p < B_ROWS) d_fix_rows[p] = row;
        }
    }
}

// exact fp32 argmax recompute for near-tie rows
__global__ void fix_kernel(const float* __restrict__ x,
                           const float* __restrict__ Wc1, const float* __restrict__ bc1,
                           const float* __restrict__ Wc2, const float* __restrict__ bc2)
{
    __shared__ float xr[D_DIM];
    __shared__ float h[D_DIM];
    __shared__ float lg[8];
    int n = d_fix_count; if (n > B_ROWS) n = B_ROWS;
    for (int i = blockIdx.x; i < n; i += gridDim.x) {
        const int row = d_fix_rows[i];
        for (int k = threadIdx.x; k < D_DIM; k += 256) xr[k] = x[(size_t)row * D_DIM + k];
        __syncthreads();
        for (int j = threadIdx.x; j < D_DIM; j += 256) {
            float s = bc1[j];
            for (int k = 0; k < D_DIM; k++) s = fmaf(xr[k], Wc1[(size_t)k * D_DIM + j], s);
            h[j] = fmaxf(s, 0.f);
        }
        __syncthreads();
        const int w = threadIdx.x >> 5, l = threadIdx.x & 31;
        if (w < 7) {
            float s = 0.f;
            for (int k = l; k < D_DIM; k += 32) s = fmaf(h[k], Wc2[k * 7 + w], s);
            #pragma unroll
            for (int off = 16; off; off >>= 1) s += __shfl_xor_sync(0xffffffffu, s, off);
            if (!l) lg[w] = s + bc2[w];
        }
        __syncthreads();
        if (threadIdx.x == 0) {
            int idx = 0; float best = lg[0];
            #pragma unroll
            for (int c = 1; c < 7; c++) if (lg[c] > best) { best = lg[c]; idx = c; }
            d_size_idx[row] = idx;
        }
        __syncthreads();
    }
}

// ---------------- routing ----------------
__global__ void route_init_kernel()
{
    const int t = threadIdx.x;
    if (t < N_EXP) { d_count[t] = 0; d_cursor[t] = 0; d_off[t] = 0; }
    if (t < MAX_TILES) d_tile_expert[t] = -1;
    if (t == 0) d_fix_count = 0;
}
__global__ void perm_init_kernel()
{
    const int i = blockIdx.x * blockDim.x + threadIdx.x;
    if (i < MAX_SLOTS) d_perm[i] = -1;
}
__global__ void count_kernel()
{
    const int r = blockIdx.x * blockDim.x + threadIdx.x;
    if (r < B_ROWS) atomicAdd(&d_count[d_size_idx[r]], 1);
}
__global__ void scan_kernel()
{
    int off = 0;
    for (int e = 0; e < N_EXP; e++) {
        d_off[e] = off;
        const int tiles = (d_count[e] + 127) >> 7;
        const int base = off >> 7;
        for (int t = 0; t < tiles; t++) d_tile_expert[base + t] = e;
        off += tiles << 7;
    }
}
__global__ void scatter_kernel()
{
    const int r = blockIdx.x * blockDim.x + threadIdx.x;
    if (r < B_ROWS) {
        const int e = d_size_idx[r];
        const int pos = d_off[e] + atomicAdd(&d_cursor[e], 1);
        d_perm[pos] = r;
    }
}

// ---------------- depth final projection ----------------
__global__ void depth_final_kernel(const float* __restrict__ H2,
                                   const float* __restrict__ We3,
                                   const float* __restrict__ be3,
                                   float* __restrict__ out)
{
    const int slot = blockIdx.x * blockDim.y + threadIdx.y;
    if (slot >= MAX_SLOTS) return;
    const int e = d_tile_expert[slot >> 7];
    if (e < 0) return;
    const int p = d_perm[slot];
    if (p < 0) return;
    const int lane = threadIdx.x;
    float a0 = 0.f, a1 = 0.f, a2 = 0.f;
    const float* h = H2 + (size_t)slot * D_DIM;
    const float* w = We3 + (size_t)e * D_DIM * 3;
    for (int k = lane; k < D_DIM; k += 32) {
        const float hv = h[k];
        a0 = fmaf(hv, w[k * 3 + 0], a0);
        a1 = fmaf(hv, w[k * 3 + 1], a1);
        a2 = fmaf(hv, w[k * 3 + 2], a2);
    }
    #pragma unroll
    for (int off = 16; off; off >>= 1) {
        a0 += __shfl_xor_sync(0xffffffffu, a0, off);
        a1 += __shfl_xor_sync(0xffffffffu, a1, off);
        a2 += __shfl_xor_sync(0xffffffffu, a2, off);
    }
    if (lane == 0) {
        float* orow = out + (size_t)p * 24;
        orow[21] = a0 + be3[e * 3 + 0];
        orow[22] = a1 + be3[e * 3 + 1];
        orow[23] = a2 + be3[e * 3 + 2];
    }
}

// ---------------- launch ----------------
extern "C" void kernel_launch(void* const* d_in, const int* in_sizes, int n_in,
                              void* d_out, int out_size)
{
    const float* x   = (const float*)d_in[0];
    const float* Wc1 = (const float*)d_in[1];
    const float* bc1 = (const float*)d_in[2];
    const float* Wc2 = (const float*)d_in[3];
    const float* bc2 = (const float*)d_in[4];
    const float* Wo1 = (const float*)d_in[5];
    const float* bo1 = (const float*)d_in[6];
    const float* Wo2 = (const float*)d_in[7];
    const float* bo2 = (const float*)d_in[8];
    const float* Wr1 = (const float*)d_in[9];
    const float* br1 = (const float*)d_in[10];
    const float* Wr2 = (const float*)d_in[11];
    const float* br2 = (const float*)d_in[12];
    const float* Wa  = (const float*)d_in[13];
    const float* ba  = (const float*)d_in[14];
    const float* We1 = (const float*)d_in[15];
    const float* be1 = (const float*)d_in[16];
    const float* We2 = (const float*)d_in[17];
    const float* be2 = (const float*)d_in[18];
    const float* We3 = (const float*)d_in[19];
    const float* be3 = (const float*)d_in[20];
    float* out = (float*)d_out;

    float* buf = nullptr;
    cudaGetSymbolAddress((void**)&buf, g_buf);
    float*    HB   = buf + OFF_HB;
    unsigned* X2   = (unsigned*)(buf + OFF_X2);
    unsigned* Dfc  = (unsigned*)(buf + OFF_DFC);
    float*    H1f  = buf + OFF_H1F;
    unsigned* H12  = (unsigned*)(buf + OFF_H12);
    float*    H2   = buf + OFF_H2;
    unsigned* Wcat = (unsigned*)(buf + OFF_WCAT);
    unsigned* W2e1 = (unsigned*)(buf + OFF_WE1);
    unsigned* W2e2 = (unsigned*)(buf + OFF_WE2);
    float*    bcat = buf + OFF_BCAT;

    cudaFuncSetAttribute(gemm_hmma, cudaFuncAttributeMaxDynamicSharedMemorySize, GSMEM_SZ);

    // conversions (fp16 2-term split)
    conv_x_kernel<<<B_ROWS, 256>>>(x, X2);
    conv_wcat_kernel<<<dim3(32, 112), dim3(32, 8)>>>(Wc1, Wr1, Wa, Wo1, Wcat);
    conv_w_kernel<<<dim3(32, 32, N_EXP), dim3(32, 8)>>>(We1, W2e1, D_DIM, D_DIM);
    conv_w_kernel<<<dim3(32, 32, N_EXP), dim3(32, 8)>>>(We2, W2e2, D_DIM, D_DIM);
    bias_cat_kernel<<<14, 256>>>(bc1, br1, ba, bo1, bcat);

    // fused stage-1 GEMM: [16384 x 3584] = relu(X2 @ Wcat^T + bcat)
    gemm_hmma<<<dim3(NCAT / 128, B_ROWS / 128), 256, GSMEM_SZ>>>(
        (const __half*)X2, (const __half*)Wcat, bcat, HB, NCAT, 0, 0, 0);

    // heads + near-tie fp32 fixup + routing tables
    route_init_kernel<<<1, 256>>>();
    head_kernel<<<B_ROWS / 8, dim3(32, 8)>>>(HB, Wc2, bc2, Wo2, bo2, Wr2, br2, out);
    fix_kernel<<<64, 256>>>(x, Wc1, bc1, Wc2, bc2);
    perm_init_kernel<<<(MAX_SLOTS + 255) / 256, 256>>>();
    count_kernel<<<(B_ROWS + 255) / 256, 256>>>();
    scan_kernel<<<1, 1>>>();
    scatter_kernel<<<(B_ROWS + 255) / 256, 256>>>();

    // expert dispatch + routed expert MLP (one expert per row)
    gather_kernel<<<MAX_SLOTS, 256>>>(HB, Dfc);
    gemm_hmma<<<dim3(8, MAX_TILES), 256, GSMEM_SZ>>>(
        (const __half*)Dfc, (const __half*)W2e1, be1, H1f, D_DIM, 1,
        (long long)D_DIM * K2, D_DIM);
    conv_h1_kernel<<<MAX_SLOTS, 256>>>(H1f, H12);
    gemm_hmma<<<dim3(8, MAX_TILES), 256, GSMEM_SZ>>>(
        (const __half*)H12, (const __half*)W2e2, be2, H2, D_DIM, 1,
        (long long)D_DIM * K2, D_DIM);

    // final 1024x3 projection scattered into output rows
    depth_final_kernel<<<MAX_SLOTS / 8, dim3(32, 8)>>>(H2, We3, be3, out);
}

// round 7
// speedup vs baseline: 1.8669x; 1.3451x over previous
#include <cuda_runtime.h>
#include <cuda_fp16.h>
#include <math.h>
#include <stdint.h>

// ---------------- constants ----------------
#define B_ROWS   16384
#define D_DIM    1024
#define KDIM     1024           // plain fp16 K
#define KU       512            // uints per fp16 row
#define NCAT     3584           // 1024(Wc1)+1024(Wr1)+1024(Wa)+512(Wo1)
#define ORD_H    512
#define N_EXP    7
#define MAX_TILES 136
#define MAX_SLOTS (MAX_TILES*128)
#define KITERS   32             // KDIM / 32

// ---------------- scratch (floats) ----------------
#define OFF_HB    0LL                      // Hbig [16384][3584] fp32
#define OFF_X2    58720256LL               // X fp16 [16384][1024] (512 uints/row)
#define OFF_DFC   67108864LL               // Dfc fp16 [17408][1024]
#define OFF_H1F   76021760LL               // H1 fp32 [17408][1024]
#define OFF_H12   93847552LL               // H1 fp16 [17408][1024]
#define OFF_H2    102760448LL              // H2 fp32 [17408][1024]
#define OFF_WCAT  120586240LL              // Wcat fp16 [3584][1024]
#define OFF_WE1   122421248LL              // We1 fp16 [7][1024][1024]
#define OFF_WE2   126091264LL
#define OFF_BCAT  129761280LL              // bcat fp32 [3584]
#define TOTAL_F   129764864LL

__device__ __align__(1024) float g_buf[TOTAL_F];

__device__ int d_size_idx[B_ROWS];
__device__ int d_perm[MAX_SLOTS];
__device__ int d_tile_expert[MAX_TILES];
__device__ int d_count[N_EXP];
__device__ int d_cursor[N_EXP];
__device__ int d_off[N_EXP];
__device__ int d_fix_count;
__device__ int d_fix_rows[B_ROWS];

// ---------------- baseline-PTX helpers ----------------
__device__ __forceinline__ uint32_t smem_to_u32(const void* p) {
    uint32_t a;
    asm("{ .reg .u64 t; cvta.to.shared.u64 t, %1; cvt.u32.u64 %0, t; }" : "=r"(a) : "l"(p));
    return a;
}
#define CP_ASYNC16(dst, src) \
    asm volatile("cp.async.cg.shared.global [%0], [%1], 16;" :: "r"(dst), "l"(src))
#define CP_COMMIT() asm volatile("cp.async.commit_group;" ::: "memory")
#define CP_WAIT2()  asm volatile("cp.async.wait_group 2;" ::: "memory")

#define LDSM_X4(r0, r1, r2, r3, addr) \
    asm volatile("ldmatrix.sync.aligned.m8n8.x4.shared.b16 {%0,%1,%2,%3}, [%4];" \
        : "=r"(r0), "=r"(r1), "=r"(r2), "=r"(r3) : "r"(addr))

#define MMA_F16(d, a, b) \
    asm volatile("mma.sync.aligned.m16n8k16.row.col.f32.f16.f16.f32 " \
        "{%0,%1,%2,%3}, {%4,%5,%6,%7}, {%8,%9}, {%0,%1,%2,%3};" \
        : "+f"((d)[0]), "+f"((d)[1]), "+f"((d)[2]), "+f"((d)[3]) \
        : "r"((a)[0]), "r"((a)[1]), "r"((a)[2]), "r"((a)[3]), "r"((b)[0]), "r"((b)[1]))

// pack two fp32 into one uint of 2 fp16
__device__ __forceinline__ unsigned pack2(float a, float b) {
    const unsigned ha = (unsigned)__half_as_ushort(__float2half_rn(a));
    const unsigned hb = (unsigned)__half_as_ushort(__float2half_rn(b));
    return ha | (hb << 16);
}

// ---------------- conversions ----------------
// fp32 rows -> fp16 rows (thread: one float4 -> one uint2)
__global__ void conv_f2h_kernel(const float* __restrict__ in, uint2* __restrict__ out)
{
    const size_t i = (size_t)blockIdx.x * 256 + threadIdx.x;   // float4 index
    const float4 v = reinterpret_cast<const float4*>(in)[i];
    out[i] = make_uint2(pack2(v.x, v.y), pack2(v.z, v.w));
}

// W [K,N] fp32 -> out [N][K] fp16 (transpose); grid.z = expert
// block covers 64 k x 32 n
__global__ void conv_w_kernel(const float* __restrict__ W, unsigned* __restrict__ out,
                              int K, int N)
{
    __shared__ float t[64][33];
    const int k0 = blockIdx.x * 64, n0 = blockIdx.y * 32;
    W   += (size_t)blockIdx.z * K * N;
    out += (size_t)blockIdx.z * N * (K / 2);
    for (int r = threadIdx.y; r < 64; r += 8)
        t[r][threadIdx.x] = W[(size_t)(k0 + r) * N + n0 + threadIdx.x];
    __syncthreads();
    for (int r = threadIdx.y; r < 32; r += 8)
        out[(size_t)(n0 + r) * (K / 2) + k0 / 2 + threadIdx.x] =
            pack2(t[2 * threadIdx.x][r], t[2 * threadIdx.x + 1][r]);
}

// fused conversion of all four stage-1 weights into Wcat [3584][1024] fp16
__global__ void conv_wcat_kernel(const float* __restrict__ Wc1, const float* __restrict__ Wr1,
                                 const float* __restrict__ Wa, const float* __restrict__ Wo1,
                                 unsigned* __restrict__ out)
{
    __shared__ float t[64][33];
    const int k0 = blockIdx.x * 64;
    const int nc0 = blockIdx.y * 32;
    const float* W; int N; int nl;
    if (nc0 < 1024)      { W = Wc1; N = 1024; nl = nc0; }
    else if (nc0 < 2048) { W = Wr1; N = 1024; nl = nc0 - 1024; }
    else if (nc0 < 3072) { W = Wa;  N = 1024; nl = nc0 - 2048; }
    else                 { W = Wo1; N = 512;  nl = nc0 - 3072; }
    for (int r = threadIdx.y; r < 64; r += 8)
        t[r][threadIdx.x] = W[(size_t)(k0 + r) * N + nl + threadIdx.x];
    __syncthreads();
    for (int r = threadIdx.y; r < 32; r += 8)
        out[(size_t)(nc0 + r) * KU + k0 / 2 + threadIdx.x] =
            pack2(t[2 * threadIdx.x][r], t[2 * threadIdx.x + 1][r]);
}

__global__ void bias_cat_kernel(const float* bc1, const float* br1,
                                const float* ba, const float* bo1, float* bcat)
{
    const int i = blockIdx.x * 256 + threadIdx.x;
    if (i < 1024)      bcat[i] = bc1[i];
    else if (i < 2048) bcat[i] = br1[i - 1024];
    else if (i < 3072) bcat[i] = ba[i - 2048];
    else if (i < 3584) bcat[i] = bo1[i - 3072];
}

// gather Df rows (Hbig cols 2048..3071) through perm -> compact fp16 rows
__global__ void gather_kernel(const float* __restrict__ HB, uint2* __restrict__ out)
{
    const int slot = blockIdx.x;
    const int p = d_perm[slot];
    uint2 o = make_uint2(0u, 0u);
    if (p >= 0) {
        const float4 v = reinterpret_cast<const float4*>(
            HB + (size_t)p * NCAT + 2048)[threadIdx.x];
        o = make_uint2(pack2(v.x, v.y), pack2(v.z, v.w));
    }
    out[(size_t)slot * 256 + threadIdx.x] = o;
}

// ---------------- HMMA GEMM: C = relu(A @ W^T + bias), fp16 in / fp32 acc ----------------
// A: [Mtiles*128][K] fp16, B: [N][K] fp16, C fp32 [., ldc]
// 256 threads / 8 warps (warp 32x64), tile 128x128, BK=32, 4-stage cp.async
#define STAGE_B   20480                // (128 A rows + 128 B rows) * 80B
#define GSMEM_SZ  (STAGE_B * 4)

__global__ __launch_bounds__(256, 2)
void gemm_hmma(const __half* __restrict__ A,
               const __half* __restrict__ Bw,
               const float* __restrict__ biasBase,
               float* __restrict__ C, int ldc,
               int useExpert, long long wStride, int biasStride)
{
    extern __shared__ __align__(128) unsigned char smem[];
    const int tileN = blockIdx.x, tileM = blockIdx.y;
    int e = 0;
    if (useExpert) { e = d_tile_expert[tileM]; if (e < 0) return; }

    const __half* Ap = A + (size_t)tileM * 128 * KDIM;
    const __half* Bp = Bw + (size_t)e * wStride + (size_t)tileN * 128 * KDIM;
    const float* bias = biasBase + (size_t)e * biasStride;

    const uint32_t sbase = smem_to_u32(smem);
    const int tid = threadIdx.x, wid = tid >> 5, lane = tid & 31;
    const int wm = wid >> 1, wn = wid & 1;
    const int lrow = lane & 15, lcol = lane >> 4;

    // cp.async mapping: 2 chunks per thread per operand (4 chunks of 16B per row)
    const int r0c = tid >> 2, s0c = tid & 3;
    const int r1c = 64 + (tid >> 2), s1c = tid & 3;

    auto issue = [&](int kt) {
        const uint32_t base = sbase + (kt & 3) * STAGE_B;
        const int k0 = kt * 32;
        CP_ASYNC16(base + r0c * 80 + s0c * 16,         Ap + (size_t)r0c * KDIM + k0 + s0c * 8);
        CP_ASYNC16(base + r1c * 80 + s1c * 16,         Ap + (size_t)r1c * KDIM + k0 + s1c * 8);
        CP_ASYNC16(base + 10240 + r0c * 80 + s0c * 16, Bp + (size_t)r0c * KDIM + k0 + s0c * 8);
        CP_ASYNC16(base + 10240 + r1c * 80 + s1c * 16, Bp + (size_t)r1c * KDIM + k0 + s1c * 8);
    };

    float acc[2][8][4] = {};

    issue(0); CP_COMMIT();
    issue(1); CP_COMMIT();
    issue(2); CP_COMMIT();

    for (int kt = 0; kt < KITERS; kt++) {
        CP_WAIT2();
        __syncthreads();
        if (kt + 3 < KITERS) issue(kt + 3);
        CP_COMMIT();

        const uint32_t ab = sbase + (kt & 3) * STAGE_B;
        const uint32_t bb = ab + 10240;
        #pragma unroll
        for (int kk = 0; kk < 2; kk++) {
            uint32_t a[2][4];
            #pragma unroll
            for (int i = 0; i < 2; i++) {
                const uint32_t addr = ab + (wm * 32 + i * 16 + lrow) * 80 + (kk * 16 + lcol * 8) * 2;
                LDSM_X4(a[i][0], a[i][1], a[i][2], a[i][3], addr);
            }
            uint32_t b[8][2];
            #pragma unroll
            for (int j4 = 0; j4 < 4; j4++) {
                uint32_t q0, q1, q2, q3;
                const uint32_t addr = bb + (wn * 64 + j4 * 16 + lrow) * 80 + (kk * 16 + lcol * 8) * 2;
                LDSM_X4(q0, q1, q2, q3, addr);
                b[2 * j4][0] = q0;     b[2 * j4][1] = q2;
                b[2 * j4 + 1][0] = q1; b[2 * j4 + 1][1] = q3;
            }
            #pragma unroll
            for (int i = 0; i < 2; i++)
                #pragma unroll
                for (int j = 0; j < 8; j++)
                    MMA_F16(acc[i][j], a[i], b[j]);
        }
    }

    // epilogue: bias + relu, float2 stores
    const int rbase = tileM * 128 + wm * 32 + (lane >> 2);
    const int cbase = tileN * 128 + wn * 64 + (lane & 3) * 2;
    #pragma unroll
    for (int j = 0; j < 8; j++) {
        const int col = cbase + j * 8;
        const float2 bz = *reinterpret_cast<const float2*>(bias + col);
        #pragma unroll
        for (int i = 0; i < 2; i++) {
            const int ra = rbase + i * 16;
            float2 v0, v1;
            v0.x = fmaxf(acc[i][j][0] + bz.x, 0.f);
            v0.y = fmaxf(acc[i][j][1] + bz.y, 0.f);
            v1.x = fmaxf(acc[i][j][2] + bz.x, 0.f);
            v1.y = fmaxf(acc[i][j][3] + bz.y, 0.f);
            *reinterpret_cast<float2*>(C + (size_t)ra * ldc + col) = v0;
            *reinterpret_cast<float2*>(C + (size_t)(ra + 8) * ldc + col) = v1;
        }
    }
}

// ---------------- fused head ----------------
__global__ void head_kernel(const float* __restrict__ HB,
                            const float* __restrict__ Wc2, const float* __restrict__ bc2,
                            const float* __restrict__ Wo2, const float* __restrict__ bo2,
                            const float* __restrict__ Wr2, const float* __restrict__ br2,
                            float* __restrict__ out)
{
    const int row = blockIdx.x * blockDim.y + threadIdx.y;
    if (row >= B_ROWS) return;
    const int lane = threadIdx.x;
    const float* hb = HB + (size_t)row * NCAT;

    float a[7] = {0,0,0,0,0,0,0};
    for (int k = lane; k < D_DIM; k += 32) {
        const float hv = hb[k]; const float* w = Wc2 + k * 7;
        #pragma unroll
        for (int c = 0; c < 7; c++) a[c] = fmaf(hv, w[c], a[c]);
    }
    float o[6] = {0,0,0,0,0,0};
    for (int k = lane; k < ORD_H; k += 32) {
        const float hv = hb[3072 + k]; const float* w = Wo2 + k * 6;
        #pragma unroll
        for (int c = 0; c < 6; c++) o[c] = fmaf(hv, w[c], o[c]);
    }
    float r = 0.f;
    for (int k = lane; k < D_DIM; k += 32) r = fmaf(hb[1024 + k], Wr2[k], r);

    #pragma unroll
    for (int off = 16; off; off >>= 1) {
        #pragma unroll
        for (int c = 0; c < 7; c++) a[c] += __shfl_xor_sync(0xffffffffu, a[c], off);
        #pragma unroll
        for (int c = 0; c < 6; c++) o[c] += __shfl_xor_sync(0xffffffffu, o[c], off);
        r += __shfl_xor_sync(0xffffffffu, r, off);
    }
    if (lane == 0) {
        float sl[7];
        #pragma unroll
        for (int c = 0; c < 7; c++) sl[c] = a[c] + bc2[c];
        float mx = sl[0];
        #pragma unroll
        for (int c = 1; c < 7; c++) mx = fmaxf(mx, sl[c]);
        float ex[7], s = 0.f;
        #pragma unroll
        for (int c = 0; c < 7; c++) { ex[c] = expf(sl[c] - mx); s += ex[c]; }
        const float inv = 1.f / s;

        float expected = 0.f;
        int idx = 0; float best = sl[0], best2 = -1e30f;
        float* orow = out + (size_t)row * 24;
        #pragma unroll
        for (int c = 0; c < 7; c++) {
            const float p = ex[c] * inv;
            expected = fmaf(p, (float)c * (1.0f / 6.0f), expected);
            orow[c] = sl[c];
            orow[14 + c] = p;
            if (c > 0) {
                if (sl[c] > best) { best2 = best; best = sl[c]; idx = c; }
                else if (sl[c] > best2) best2 = sl[c];
            }
        }
        #pragma unroll
        for (int c = 0; c < 6; c++) orow[7 + c] = o[c] + bo2[c];
        const float resid = 0.35f * tanhf(r + br2[0]);
        orow[13] = fminf(fmaxf(expected + resid, 0.f), 1.f);
        d_size_idx[row] = idx;
        if (best - best2 < 4e-3f) {
            int p = atomicAdd(&d_fix_count, 1);
            if (p < B_ROWS) d_fix_rows[p] = row;
        }
    }
}

// exact fp32 argmax recompute for near-tie rows
__global__ void fix_kernel(const float* __restrict__ x,
                           const float* __restrict__ Wc1, const float* __restrict__ bc1,
                           const float* __restrict__ Wc2, const float* __restrict__ bc2)
{
    __shared__ float xr[D_DIM];
    __shared__ float h[D_DIM];
    __shared__ float lg[8];
    int n = d_fix_count; if (n > B_ROWS) n = B_ROWS;
    for (int i = blockIdx.x; i < n; i += gridDim.x) {
        const int row = d_fix_rows[i];
        for (int k = threadIdx.x; k < D_DIM; k += 256) xr[k] = x[(size_t)row * D_DIM + k];
        __syncthreads();
        for (int j = threadIdx.x; j < D_DIM; j += 256) {
            float s = bc1[j];
            for (int k = 0; k < D_DIM; k++) s = fmaf(xr[k], Wc1[(size_t)k * D_DIM + j], s);
            h[j] = fmaxf(s, 0.f);
        }
        __syncthreads();
        const int w = threadIdx.x >> 5, l = threadIdx.x & 31;
        if (w < 7) {
            float s = 0.f;
            for (int k = l; k < D_DIM; k += 32) s = fmaf(h[k], Wc2[k * 7 + w], s);
            #pragma unroll
            for (int off = 16; off; off >>= 1) s += __shfl_xor_sync(0xffffffffu, s, off);
            if (!l) lg[w] = s + bc2[w];
        }
        __syncthreads();
        if (threadIdx.x == 0) {
            int idx = 0; float best = lg[0];
            #pragma unroll
            for (int c = 1; c < 7; c++) if (lg[c] > best) { best = lg[c]; idx = c; }
            d_size_idx[row] = idx;
        }
        __syncthreads();
    }
}

// ---------------- routing ----------------
__global__ void route_init_kernel()
{
    const int t = threadIdx.x;
    if (t < N_EXP) { d_count[t] = 0; d_cursor[t] = 0; d_off[t] = 0; }
    if (t < MAX_TILES) d_tile_expert[t] = -1;
    if (t == 0) d_fix_count = 0;
}
__global__ void perm_init_kernel()
{
    const int i = blockIdx.x * blockDim.x + threadIdx.x;
    if (i < MAX_SLOTS) d_perm[i] = -1;
}
__global__ void count_kernel()
{
    const int r = blockIdx.x * blockDim.x + threadIdx.x;
    if (r < B_ROWS) atomicAdd(&d_count[d_size_idx[r]], 1);
}
__global__ void scan_kernel()
{
    int off = 0;
    for (int e = 0; e < N_EXP; e++) {
        d_off[e] = off;
        const int tiles = (d_count[e] + 127) >> 7;
        const int base = off >> 7;
        for (int t = 0; t < tiles; t++) d_tile_expert[base + t] = e;
        off += tiles << 7;
    }
}
__global__ void scatter_kernel()
{
    const int r = blockIdx.x * blockDim.x + threadIdx.x;
    if (r < B_ROWS) {
        const int e = d_size_idx[r];
        const int pos = d_off[e] + atomicAdd(&d_cursor[e], 1);
        d_perm[pos] = r;
    }
}

// ---------------- depth final projection ----------------
__global__ void depth_final_kernel(const float* __restrict__ H2,
                                   const float* __restrict__ We3,
                                   const float* __restrict__ be3,
                                   float* __restrict__ out)
{
    const int slot = blockIdx.x * blockDim.y + threadIdx.y;
    if (slot >= MAX_SLOTS) return;
    const int e = d_tile_expert[slot >> 7];
    if (e < 0) return;
    const int p = d_perm[slot];
    if (p < 0) return;
    const int lane = threadIdx.x;
    float a0 = 0.f, a1 = 0.f, a2 = 0.f;
    const float* h = H2 + (size_t)slot * D_DIM;
    const float* w = We3 + (size_t)e * D_DIM * 3;
    for (int k = lane; k < D_DIM; k += 32) {
        const float hv = h[k];
        a0 = fmaf(hv, w[k * 3 + 0], a0);
        a1 = fmaf(hv, w[k * 3 + 1], a1);
        a2 = fmaf(hv, w[k * 3 + 2], a2);
    }
    #pragma unroll
    for (int off = 16; off; off >>= 1) {
        a0 += __shfl_xor_sync(0xffffffffu, a0, off);
        a1 += __shfl_xor_sync(0xffffffffu, a1, off);
        a2 += __shfl_xor_sync(0xffffffffu, a2, off);
    }
    if (lane == 0) {
        float* orow = out + (size_t)p * 24;
        orow[21] = a0 + be3[e * 3 + 0];
        orow[22] = a1 + be3[e * 3 + 1];
        orow[23] = a2 + be3[e * 3 + 2];
    }
}

// ---------------- launch ----------------
extern "C" void kernel_launch(void* const* d_in, const int* in_sizes, int n_in,
                              void* d_out, int out_size)
{
    const float* x   = (const float*)d_in[0];
    const float* Wc1 = (const float*)d_in[1];
    const float* bc1 = (const float*)d_in[2];
    const float* Wc2 = (const float*)d_in[3];
    const float* bc2 = (const float*)d_in[4];
    const float* Wo1 = (const float*)d_in[5];
    const float* bo1 = (const float*)d_in[6];
    const float* Wo2 = (const float*)d_in[7];
    const float* bo2 = (const float*)d_in[8];
    const float* Wr1 = (const float*)d_in[9];
    const float* br1 = (const float*)d_in[10];
    const float* Wr2 = (const float*)d_in[11];
    const float* br2 = (const float*)d_in[12];
    const float* Wa  = (const float*)d_in[13];
    const float* ba  = (const float*)d_in[14];
    const float* We1 = (const float*)d_in[15];
    const float* be1 = (const float*)d_in[16];
    const float* We2 = (const float*)d_in[17];
    const float* be2 = (const float*)d_in[18];
    const float* We3 = (const float*)d_in[19];
    const float* be3 = (const float*)d_in[20];
    float* out = (float*)d_out;

    float* buf = nullptr;
    cudaGetSymbolAddress((void**)&buf, g_buf);
    float*    HB   = buf + OFF_HB;
    unsigned* X2   = (unsigned*)(buf + OFF_X2);
    unsigned* Dfc  = (unsigned*)(buf + OFF_DFC);
    float*    H1f  = buf + OFF_H1F;
    unsigned* H12  = (unsigned*)(buf + OFF_H12);
    float*    H2   = buf + OFF_H2;
    unsigned* Wcat = (unsigned*)(buf + OFF_WCAT);
    unsigned* W2e1 = (unsigned*)(buf + OFF_WE1);
    unsigned* W2e2 = (unsigned*)(buf + OFF_WE2);
    float*    bcat = buf + OFF_BCAT;

    cudaFuncSetAttribute(gemm_hmma, cudaFuncAttributeMaxDynamicSharedMemorySize, GSMEM_SZ);

    // conversions (plain fp16)
    conv_f2h_kernel<<<B_ROWS, 256>>>(x, (uint2*)X2);
    conv_wcat_kernel<<<dim3(16, 112), dim3(32, 8)>>>(Wc1, Wr1, Wa, Wo1, Wcat);
    conv_w_kernel<<<dim3(16, 32, N_EXP), dim3(32, 8)>>>(We1, W2e1, D_DIM, D_DIM);
    conv_w_kernel<<<dim3(16, 32, N_EXP), dim3(32, 8)>>>(We2, W2e2, D_DIM, D_DIM);
    bias_cat_kernel<<<14, 256>>>(bc1, br1, ba, bo1, bcat);

    // fused stage-1 GEMM: [16384 x 3584] = relu(X @ Wcat^T + bcat)
    gemm_hmma<<<dim3(NCAT / 128, B_ROWS / 128), 256, GSMEM_SZ>>>(
        (const __half*)X2, (const __half*)Wcat, bcat, HB, NCAT, 0, 0, 0);

    // heads + near-tie fp32 fixup + routing tables
    route_init_kernel<<<1, 256>>>();
    head_kernel<<<B_ROWS / 8, dim3(32, 8)>>>(HB, Wc2, bc2, Wo2, bo2, Wr2, br2, out);
    fix_kernel<<<64, 256>>>(x, Wc1, bc1, Wc2, bc2);
    perm_init_kernel<<<(MAX_SLOTS + 255) / 256, 256>>>();
    count_kernel<<<(B_ROWS + 255) / 256, 256>>>();
    scan_kernel<<<1, 1>>>();
    scatter_kernel<<<(B_ROWS + 255) / 256, 256>>>();

    // expert dispatch + routed expert MLP (one expert per row)
    gather_kernel<<<MAX_SLOTS, 256>>>(HB, (uint2*)Dfc);
    gemm_hmma<<<dim3(8, MAX_TILES), 256, GSMEM_SZ>>>(
        (const __half*)Dfc, (const __half*)W2e1, be1, H1f, D_DIM, 1,
        (long long)D_DIM * KDIM, D_DIM);
    conv_f2h_kernel<<<MAX_SLOTS, 256>>>(H1f, (uint2*)H12);
    gemm_hmma<<<dim3(8, MAX_TILES), 256, GSMEM_SZ>>>(
        (const __half*)H12, (const __half*)W2e2, be2, H2, D_DIM, 1,
        (long long)D_DIM * KDIM, D_DIM);

    // final 1024x3 projection scattered into output rows
    depth_final_kernel<<<MAX_SLOTS / 8, dim3(32, 8)>>>(H2, We3, be3, out);
}

// round 8
// speedup vs baseline: 1.8938x; 1.0144x over previous
#include <cuda_runtime.h>
#include <cuda_fp16.h>
#include <math.h>
#include <stdint.h>

// ---------------- constants ----------------
#define B_ROWS   16384
#define D_DIM    1024
#define KDIM     1024           // fp16 K
#define KU       512            // uints per fp16 row
#define NCAT     3584           // 1024(Wc1)+1024(Wr1)+1024(Wa)+512(Wo1)
#define ORD_H    512
#define N_EXP    7
#define MAX_TILES 136
#define MAX_SLOTS (MAX_TILES*128)
#define KITERS   32             // KDIM / 32

// ---------------- scratch (float units) ----------------
#define OFF_HB    0LL                      // HB fp16 [16384][3584]
#define OFF_X2    29360128LL               // X fp16 [16384][1024]
#define OFF_DFC   37748736LL               // Dfc fp16 [17408][1024]
#define OFF_H12   46661632LL               // H1 fp16 [17408][1024]
#define OFF_H2    55574528LL               // H2 fp16 [17408][1024]
#define OFF_WCAT  64487424LL               // Wcat fp16 [3584][1024]
#define OFF_WE1   66322432LL               // We1 fp16 [7][1024][1024]
#define OFF_WE2   69992448LL
#define OFF_BCAT  73662464LL               // bcat fp32 [3584]
#define TOTAL_F   73666048LL

__device__ __align__(1024) float g_buf[TOTAL_F];

__device__ int d_size_idx[B_ROWS];
__device__ int d_perm[MAX_SLOTS];
__device__ int d_tile_expert[MAX_TILES];
__device__ int d_count[N_EXP];
__device__ int d_cursor[N_EXP];
__device__ int d_off[N_EXP];
__device__ int d_fix_count;
__device__ int d_fix_rows[B_ROWS];

// ---------------- baseline-PTX helpers ----------------
__device__ __forceinline__ uint32_t smem_to_u32(const void* p) {
    uint32_t a;
    asm("{ .reg .u64 t; cvta.to.shared.u64 t, %1; cvt.u32.u64 %0, t; }" : "=r"(a) : "l"(p));
    return a;
}
#define CP_ASYNC16(dst, src) \
    asm volatile("cp.async.cg.shared.global [%0], [%1], 16;" :: "r"(dst), "l"(src))
#define CP_COMMIT() asm volatile("cp.async.commit_group;" ::: "memory")
#define CP_WAIT2()  asm volatile("cp.async.wait_group 2;" ::: "memory")

#define LDSM_X4(r0, r1, r2, r3, addr) \
    asm volatile("ldmatrix.sync.aligned.m8n8.x4.shared.b16 {%0,%1,%2,%3}, [%4];" \
        : "=r"(r0), "=r"(r1), "=r"(r2), "=r"(r3) : "r"(addr))

#define MMA_F16(d, a, b) \
    asm volatile("mma.sync.aligned.m16n8k16.row.col.f32.f16.f16.f32 " \
        "{%0,%1,%2,%3}, {%4,%5,%6,%7}, {%8,%9}, {%0,%1,%2,%3};" \
        : "+f"((d)[0]), "+f"((d)[1]), "+f"((d)[2]), "+f"((d)[3]) \
        : "r"((a)[0]), "r"((a)[1]), "r"((a)[2]), "r"((a)[3]), "r"((b)[0]), "r"((b)[1]))

// pack two fp32 into one uint of 2 fp16
__device__ __forceinline__ unsigned pack2(float a, float b) {
    const unsigned ha = (unsigned)__half_as_ushort(__float2half_rn(a));
    const unsigned hb = (unsigned)__half_as_ushort(__float2half_rn(b));
    return ha | (hb << 16);
}

// ---------------- conversions ----------------
// fp32 rows -> fp16 rows (thread: one float4 -> one uint2)
__global__ void conv_f2h_kernel(const float* __restrict__ in, uint2* __restrict__ out)
{
    const size_t i = (size_t)blockIdx.x * 256 + threadIdx.x;   // float4 index
    const float4 v = reinterpret_cast<const float4*>(in)[i];
    out[i] = make_uint2(pack2(v.x, v.y), pack2(v.z, v.w));
}

// W [K,N] fp32 -> out [N][K] fp16 (transpose); grid.z = expert
__global__ void conv_w_kernel(const float* __restrict__ W, unsigned* __restrict__ out,
                              int K, int N)
{
    __shared__ float t[64][33];
    const int k0 = blockIdx.x * 64, n0 = blockIdx.y * 32;
    W   += (size_t)blockIdx.z * K * N;
    out += (size_t)blockIdx.z * N * (K / 2);
    for (int r = threadIdx.y; r < 64; r += 8)
        t[r][threadIdx.x] = W[(size_t)(k0 + r) * N + n0 + threadIdx.x];
    __syncthreads();
    for (int r = threadIdx.y; r < 32; r += 8)
        out[(size_t)(n0 + r) * (K / 2) + k0 / 2 + threadIdx.x] =
            pack2(t[2 * threadIdx.x][r], t[2 * threadIdx.x + 1][r]);
}

// fused conversion of all four stage-1 weights into Wcat [3584][1024] fp16
__global__ void conv_wcat_kernel(const float* __restrict__ Wc1, const float* __restrict__ Wr1,
                                 const float* __restrict__ Wa, const float* __restrict__ Wo1,
                                 unsigned* __restrict__ out)
{
    __shared__ float t[64][33];
    const int k0 = blockIdx.x * 64;
    const int nc0 = blockIdx.y * 32;
    const float* W; int N; int nl;
    if (nc0 < 1024)      { W = Wc1; N = 1024; nl = nc0; }
    else if (nc0 < 2048) { W = Wr1; N = 1024; nl = nc0 - 1024; }
    else if (nc0 < 3072) { W = Wa;  N = 1024; nl = nc0 - 2048; }
    else                 { W = Wo1; N = 512;  nl = nc0 - 3072; }
    for (int r = threadIdx.y; r < 64; r += 8)
        t[r][threadIdx.x] = W[(size_t)(k0 + r) * N + nl + threadIdx.x];
    __syncthreads();
    for (int r = threadIdx.y; r < 32; r += 8)
        out[(size_t)(nc0 + r) * KU + k0 / 2 + threadIdx.x] =
            pack2(t[2 * threadIdx.x][r], t[2 * threadIdx.x + 1][r]);
}

__global__ void bias_cat_kernel(const float* bc1, const float* br1,
                                const float* ba, const float* bo1, float* bcat)
{
    const int i = blockIdx.x * 256 + threadIdx.x;
    if (i < 1024)      bcat[i] = bc1[i];
    else if (i < 2048) bcat[i] = br1[i - 1024];
    else if (i < 3072) bcat[i] = ba[i - 2048];
    else if (i < 3584) bcat[i] = bo1[i - 3072];
}

// gather Df fp16 rows (HB half-cols 2048..3071) through perm -> compact fp16 rows
__global__ void gather_kernel(const __half* __restrict__ HBh, uint4* __restrict__ out)
{
    const int slot = blockIdx.x;
    const int p = d_perm[slot];
    uint4 o = make_uint4(0u, 0u, 0u, 0u);
    if (p >= 0)
        o = reinterpret_cast<const uint4*>(HBh + (size_t)p * NCAT + 2048)[threadIdx.x];
    out[(size_t)slot * 128 + threadIdx.x] = o;
}

// ---------------- HMMA GEMM: C = relu(A @ W^T + bias), fp16 in / fp32 acc ----------------
// 256 threads / 8 warps (warp 32x64), tile 128x128, BK=32, 4-stage cp.async
// outHalf: 0 -> fp32 C, 1 -> fp16-packed C (ldc in elements either way)
#define STAGE_B   20480
#define GSMEM_SZ  (STAGE_B * 4)

__global__ __launch_bounds__(256, 2)
void gemm_hmma(const __half* __restrict__ A,
               const __half* __restrict__ Bw,
               const float* __restrict__ biasBase,
               void* __restrict__ Cv, int ldc,
               int useExpert, long long wStride, int biasStride, int outHalf)
{
    extern __shared__ __align__(128) unsigned char smem[];
    const int tileN = blockIdx.x, tileM = blockIdx.y;
    int e = 0;
    if (useExpert) { e = d_tile_expert[tileM]; if (e < 0) return; }

    const __half* Ap = A + (size_t)tileM * 128 * KDIM;
    const __half* Bp = Bw + (size_t)e * wStride + (size_t)tileN * 128 * KDIM;
    const float* bias = biasBase + (size_t)e * biasStride;

    const uint32_t sbase = smem_to_u32(smem);
    const int tid = threadIdx.x, wid = tid >> 5, lane = tid & 31;
    const int wm = wid >> 1, wn = wid & 1;
    const int lrow = lane & 15, lcol = lane >> 4;

    const int r0c = tid >> 2, s0c = tid & 3;
    const int r1c = 64 + (tid >> 2), s1c = tid & 3;

    auto issue = [&](int kt) {
        const uint32_t base = sbase + (kt & 3) * STAGE_B;
        const int k0 = kt * 32;
        CP_ASYNC16(base + r0c * 80 + s0c * 16,         Ap + (size_t)r0c * KDIM + k0 + s0c * 8);
        CP_ASYNC16(base + r1c * 80 + s1c * 16,         Ap + (size_t)r1c * KDIM + k0 + s1c * 8);
        CP_ASYNC16(base + 10240 + r0c * 80 + s0c * 16, Bp + (size_t)r0c * KDIM + k0 + s0c * 8);
        CP_ASYNC16(base + 10240 + r1c * 80 + s1c * 16, Bp + (size_t)r1c * KDIM + k0 + s1c * 8);
    };

    float acc[2][8][4] = {};

    issue(0); CP_COMMIT();
    issue(1); CP_COMMIT();
    issue(2); CP_COMMIT();

    for (int kt = 0; kt < KITERS; kt++) {
        CP_WAIT2();
        __syncthreads();
        if (kt + 3 < KITERS) issue(kt + 3);
        CP_COMMIT();

        const uint32_t ab = sbase + (kt & 3) * STAGE_B;
        const uint32_t bb = ab + 10240;
        #pragma unroll
        for (int kk = 0; kk < 2; kk++) {
            uint32_t a[2][4];
            #pragma unroll
            for (int i = 0; i < 2; i++) {
                const uint32_t addr = ab + (wm * 32 + i * 16 + lrow) * 80 + (kk * 16 + lcol * 8) * 2;
                LDSM_X4(a[i][0], a[i][1], a[i][2], a[i][3], addr);
            }
            uint32_t b[8][2];
            #pragma unroll
            for (int j4 = 0; j4 < 4; j4++) {
                uint32_t q0, q1, q2, q3;
                const uint32_t addr = bb + (wn * 64 + j4 * 16 + lrow) * 80 + (kk * 16 + lcol * 8) * 2;
                LDSM_X4(q0, q1, q2, q3, addr);
                b[2 * j4][0] = q0;     b[2 * j4][1] = q2;
                b[2 * j4 + 1][0] = q1; b[2 * j4 + 1][1] = q3;
            }
            #pragma unroll
            for (int i = 0; i < 2; i++)
                #pragma unroll
                for (int j = 0; j < 8; j++)
                    MMA_F16(acc[i][j], a[i], b[j]);
        }
    }

    // epilogue: bias + relu
    const int rbase = tileM * 128 + wm * 32 + (lane >> 2);
    const int cbase = tileN * 128 + wn * 64 + (lane & 3) * 2;
    if (outHalf) {
        unsigned* C16 = (unsigned*)Cv;
        const int ldu = ldc >> 1;
        #pragma unroll
        for (int j = 0; j < 8; j++) {
            const int col = cbase + j * 8;
            const float2 bz = *reinterpret_cast<const float2*>(bias + col);
            #pragma unroll
            for (int i = 0; i < 2; i++) {
                const int ra = rbase + i * 16;
                C16[(size_t)ra * ldu + (col >> 1)] =
                    pack2(fmaxf(acc[i][j][0] + bz.x, 0.f), fmaxf(acc[i][j][1] + bz.y, 0.f));
                C16[(size_t)(ra + 8) * ldu + (col >> 1)] =
                    pack2(fmaxf(acc[i][j][2] + bz.x, 0.f), fmaxf(acc[i][j][3] + bz.y, 0.f));
            }
        }
    } else {
        float* C = (float*)Cv;
        #pragma unroll
        for (int j = 0; j < 8; j++) {
            const int col = cbase + j * 8;
            const float2 bz = *reinterpret_cast<const float2*>(bias + col);
            #pragma unroll
            for (int i = 0; i < 2; i++) {
                const int ra = rbase + i * 16;
                float2 v0, v1;
                v0.x = fmaxf(acc[i][j][0] + bz.x, 0.f);
                v0.y = fmaxf(acc[i][j][1] + bz.y, 0.f);
                v1.x = fmaxf(acc[i][j][2] + bz.x, 0.f);
                v1.y = fmaxf(acc[i][j][3] + bz.y, 0.f);
                *reinterpret_cast<float2*>(C + (size_t)ra * ldc + col) = v0;
                *reinterpret_cast<float2*>(C + (size_t)(ra + 8) * ldc + col) = v1;
            }
        }
    }
}

// ---------------- fused head (fp16 inputs) ----------------
__global__ void head_kernel(const __half* __restrict__ HBh,
                            const float* __restrict__ Wc2, const float* __restrict__ bc2,
                            const float* __restrict__ Wo2, const float* __restrict__ bo2,
                            const float* __restrict__ Wr2, const float* __restrict__ br2,
                            float* __restrict__ out)
{
    const int row = blockIdx.x * blockDim.y + threadIdx.y;
    if (row >= B_ROWS) return;
    const int lane = threadIdx.x;
    const __half2* h2 = reinterpret_cast<const __half2*>(HBh + (size_t)row * NCAT);

    float a[7] = {0,0,0,0,0,0,0};
    for (int k2 = lane; k2 < 512; k2 += 32) {
        const float2 hv = __half22float2(h2[k2]);
        const float* w = Wc2 + (2 * k2) * 7;
        #pragma unroll
        for (int c = 0; c < 7; c++) a[c] += hv.x * w[c] + hv.y * w[7 + c];
    }
    float o[6] = {0,0,0,0,0,0};
    for (int k2 = lane; k2 < 256; k2 += 32) {
        const float2 hv = __half22float2(h2[1536 + k2]);
        const float* w = Wo2 + (2 * k2) * 6;
        #pragma unroll
        for (int c = 0; c < 6; c++) o[c] += hv.x * w[c] + hv.y * w[6 + c];
    }
    float r = 0.f;
    for (int k2 = lane; k2 < 512; k2 += 32) {
        const float2 hv = __half22float2(h2[512 + k2]);
        r += hv.x * Wr2[2 * k2] + hv.y * Wr2[2 * k2 + 1];
    }

    #pragma unroll
    for (int off = 16; off; off >>= 1) {
        #pragma unroll
        for (int c = 0; c < 7; c++) a[c] += __shfl_xor_sync(0xffffffffu, a[c], off);
        #pragma unroll
        for (int c = 0; c < 6; c++) o[c] += __shfl_xor_sync(0xffffffffu, o[c], off);
        r += __shfl_xor_sync(0xffffffffu, r, off);
    }
    if (lane == 0) {
        float sl[7];
        #pragma unroll
        for (int c = 0; c < 7; c++) sl[c] = a[c] + bc2[c];
        float mx = sl[0];
        #pragma unroll
        for (int c = 1; c < 7; c++) mx = fmaxf(mx, sl[c]);
        float ex[7], s = 0.f;
        #pragma unroll
        for (int c = 0; c < 7; c++) { ex[c] = expf(sl[c] - mx); s += ex[c]; }
        const float inv = 1.f / s;

        float expected = 0.f;
        int idx = 0; float best = sl[0], best2 = -1e30f;
        float* orow = out + (size_t)row * 24;
        #pragma unroll
        for (int c = 0; c < 7; c++) {
            const float p = ex[c] * inv;
            expected = fmaf(p, (float)c * (1.0f / 6.0f), expected);
            orow[c] = sl[c];
            orow[14 + c] = p;
            if (c > 0) {
                if (sl[c] > best) { best2 = best; best = sl[c]; idx = c; }
                else if (sl[c] > best2) best2 = sl[c];
            }
        }
        #pragma unroll
        for (int c = 0; c < 6; c++) orow[7 + c] = o[c] + bo2[c];
        const float resid = 0.35f * tanhf(r + br2[0]);
        orow[13] = fminf(fmaxf(expected + resid, 0.f), 1.f);
        d_size_idx[row] = idx;
        if (best - best2 < 4e-3f) {
            int p = atomicAdd(&d_fix_count, 1);
            if (p < B_ROWS) d_fix_rows[p] = row;
        }
    }
}

// exact fp32 argmax recompute for near-tie rows
__global__ void fix_kernel(const float* __restrict__ x,
                           const float* __restrict__ Wc1, const float* __restrict__ bc1,
                           const float* __restrict__ Wc2, const float* __restrict__ bc2)
{
    __shared__ float xr[D_DIM];
    __shared__ float h[D_DIM];
    __shared__ float lg[8];
    int n = d_fix_count; if (n > B_ROWS) n = B_ROWS;
    for (int i = blockIdx.x; i < n; i += gridDim.x) {
        const int row = d_fix_rows[i];
        for (int k = threadIdx.x; k < D_DIM; k += 256) xr[k] = x[(size_t)row * D_DIM + k];
        __syncthreads();
        for (int j = threadIdx.x; j < D_DIM; j += 256) {
            float s = bc1[j];
            for (int k = 0; k < D_DIM; k++) s = fmaf(xr[k], Wc1[(size_t)k * D_DIM + j], s);
            h[j] = fmaxf(s, 0.f);
        }
        __syncthreads();
        const int w = threadIdx.x >> 5, l = threadIdx.x & 31;
        if (w < 7) {
            float s = 0.f;
            for (int k = l; k < D_DIM; k += 32) s = fmaf(h[k], Wc2[k * 7 + w], s);
            #pragma unroll
            for (int off = 16; off; off >>= 1) s += __shfl_xor_sync(0xffffffffu, s, off);
            if (!l) lg[w] = s + bc2[w];
        }
        __syncthreads();
        if (threadIdx.x == 0) {
            int idx = 0; float best = lg[0];
            #pragma unroll
            for (int c = 1; c < 7; c++) if (lg[c] > best) { best = lg[c]; idx = c; }
            d_size_idx[row] = idx;
        }
        __syncthreads();
    }
}

// ---------------- routing ----------------
__global__ void route_init_kernel()
{
    const int t = threadIdx.x;
    if (t < N_EXP) { d_count[t] = 0; d_cursor[t] = 0; d_off[t] = 0; }
    if (t < MAX_TILES) d_tile_expert[t] = -1;
    if (t == 0) d_fix_count = 0;
}
__global__ void perm_init_kernel()
{
    const int i = blockIdx.x * blockDim.x + threadIdx.x;
    if (i < MAX_SLOTS) d_perm[i] = -1;
}
__global__ void count_kernel()
{
    const int r = blockIdx.x * blockDim.x + threadIdx.x;
    if (r < B_ROWS) atomicAdd(&d_count[d_size_idx[r]], 1);
}
__global__ void scan_kernel()
{
    int off = 0;
    for (int e = 0; e < N_EXP; e++) {
        d_off[e] = off;
        const int tiles = (d_count[e] + 127) >> 7;
        const int base = off >> 7;
        for (int t = 0; t < tiles; t++) d_tile_expert[base + t] = e;
        off += tiles << 7;
    }
}
__global__ void scatter_kernel()
{
    const int r = blockIdx.x * blockDim.x + threadIdx.x;
    if (r < B_ROWS) {
        const int e = d_size_idx[r];
        const int pos = d_off[e] + atomicAdd(&d_cursor[e], 1);
        d_perm[pos] = r;
    }
}

// ---------------- depth final projection (fp16 input) ----------------
__global__ void depth_final_kernel(const __half* __restrict__ H2h,
                                   const float* __restrict__ We3,
                                   const float* __restrict__ be3,
                                   float* __restrict__ out)
{
    const int slot = blockIdx.x * blockDim.y + threadIdx.y;
    if (slot >= MAX_SLOTS) return;
    const int e = d_tile_expert[slot >> 7];
    if (e < 0) return;
    const int p = d_perm[slot];
    if (p < 0) return;
    const int lane = threadIdx.x;
    float a0 = 0.f, a1 = 0.f, a2 = 0.f;
    const __half2* h2 = reinterpret_cast<const __half2*>(H2h + (size_t)slot * D_DIM);
    const float* w = We3 + (size_t)e * D_DIM * 3;
    for (int k2 = lane; k2 < 512; k2 += 32) {
        const float2 hv = __half22float2(h2[k2]);
        const int k = 2 * k2;
        a0 += hv.x * w[k * 3 + 0] + hv.y * w[k * 3 + 3];
        a1 += hv.x * w[k * 3 + 1] + hv.y * w[k * 3 + 4];
        a2 += hv.x * w[k * 3 + 2] + hv.y * w[k * 3 + 5];
    }
    #pragma unroll
    for (int off = 16; off; off >>= 1) {
        a0 += __shfl_xor_sync(0xffffffffu, a0, off);
        a1 += __shfl_xor_sync(0xffffffffu, a1, off);
        a2 += __shfl_xor_sync(0xffffffffu, a2, off);
    }
    if (lane == 0) {
        float* orow = out + (size_t)p * 24;
        orow[21] = a0 + be3[e * 3 + 0];
        orow[22] = a1 + be3[e * 3 + 1];
        orow[23] = a2 + be3[e * 3 + 2];
    }
}

// ---------------- launch ----------------
extern "C" void kernel_launch(void* const* d_in, const int* in_sizes, int n_in,
                              void* d_out, int out_size)
{
    const float* x   = (const float*)d_in[0];
    const float* Wc1 = (const float*)d_in[1];
    const float* bc1 = (const float*)d_in[2];
    const float* Wc2 = (const float*)d_in[3];
    const float* bc2 = (const float*)d_in[4];
    const float* Wo1 = (const float*)d_in[5];
    const float* bo1 = (const float*)d_in[6];
    const float* Wo2 = (const float*)d_in[7];
    const float* bo2 = (const float*)d_in[8];
    const float* Wr1 = (const float*)d_in[9];
    const float* br1 = (const float*)d_in[10];
    const float* Wr2 = (const float*)d_in[11];
    const float* br2 = (const float*)d_in[12];
    const float* Wa  = (const float*)d_in[13];
    const float* ba  = (const float*)d_in[14];
    const float* We1 = (const float*)d_in[15];
    const float* be1 = (const float*)d_in[16];
    const float* We2 = (const float*)d_in[17];
    const float* be2 = (const float*)d_in[18];
    const float* We3 = (const float*)d_in[19];
    const float* be3 = (const float*)d_in[20];
    float* out = (float*)d_out;

    float* buf = nullptr;
    cudaGetSymbolAddress((void**)&buf, g_buf);
    __half*   HBh  = (__half*)(buf + OFF_HB);
    unsigned* X2   = (unsigned*)(buf + OFF_X2);
    unsigned* Dfc  = (unsigned*)(buf + OFF_DFC);
    unsigned* H12  = (unsigned*)(buf + OFF_H12);
    __half*   H2h  = (__half*)(buf + OFF_H2);
    unsigned* Wcat = (unsigned*)(buf + OFF_WCAT);
    unsigned* W2e1 = (unsigned*)(buf + OFF_WE1);
    unsigned* W2e2 = (unsigned*)(buf + OFF_WE2);
    float*    bcat = buf + OFF_BCAT;

    cudaFuncSetAttribute(gemm_hmma, cudaFuncAttributeMaxDynamicSharedMemorySize, GSMEM_SZ);

    // conversions (plain fp16)
    conv_f2h_kernel<<<B_ROWS, 256>>>(x, (uint2*)X2);
    conv_wcat_kernel<<<dim3(16, 112), dim3(32, 8)>>>(Wc1, Wr1, Wa, Wo1, Wcat);
    conv_w_kernel<<<dim3(16, 32, N_EXP), dim3(32, 8)>>>(We1, W2e1, D_DIM, D_DIM);
    conv_w_kernel<<<dim3(16, 32, N_EXP), dim3(32, 8)>>>(We2, W2e2, D_DIM, D_DIM);
    bias_cat_kernel<<<14, 256>>>(bc1, br1, ba, bo1, bcat);

    // fused stage-1 GEMM: HB(fp16) = relu(X @ Wcat^T + bcat)
    gemm_hmma<<<dim3(NCAT / 128, B_ROWS / 128), 256, GSMEM_SZ>>>(
        (const __half*)X2, (const __half*)Wcat, bcat, HBh, NCAT, 0, 0, 0, 1);

    // heads + near-tie fp32 fixup + routing tables
    route_init_kernel<<<1, 256>>>();
    head_kernel<<<B_ROWS / 8, dim3(32, 8)>>>(HBh, Wc2, bc2, Wo2, bo2, Wr2, br2, out);
    fix_kernel<<<64, 256>>>(x, Wc1, bc1, Wc2, bc2);
    perm_init_kernel<<<(MAX_SLOTS + 255) / 256, 256>>>();
    count_kernel<<<(B_ROWS + 255) / 256, 256>>>();
    scan_kernel<<<1, 1>>>();
    scatter_kernel<<<(B_ROWS + 255) / 256, 256>>>();

    // expert dispatch + routed expert MLP (one expert per row, fp16 throughout)
    gather_kernel<<<MAX_SLOTS, 128>>>(HBh, (uint4*)Dfc);
    gemm_hmma<<<dim3(8, MAX_TILES), 256, GSMEM_SZ>>>(
        (const __half*)Dfc, (const __half*)W2e1, be1, H12, D_DIM, 1,
        (long long)D_DIM * KDIM, D_DIM, 1);
    gemm_hmma<<<dim3(8, MAX_TILES), 256, GSMEM_SZ>>>(
        (const __half*)H12, (const __half*)W2e2, be2, H2h, D_DIM, 1,
        (long long)D_DIM * KDIM, D_DIM, 1);

    // final 1024x3 projection scattered into output rows
    depth_final_kernel<<<MAX_SLOTS / 8, dim3(32, 8)>>>(H2h, We3, be3, out);
}